// round 12
// baseline (speedup 1.0000x reference)
#include <cuda_runtime.h>
#include <cuda_bf16.h>
#include <math.h>
#include <stdint.h>

// Problem constants
constexpr int B_   = 256;
constexpr int L_   = 100;
constexpr int C_   = 55;
constexpr int D_   = 512;
constexpr int H_   = 8;
constexpr int NL_  = 3;
constexpr int DFF_ = 64;
constexpr int DK_  = D_ / H_;      // 64
constexpr int BL_  = B_ * L_;      // 25600
constexpr int KC_  = 3 * C_;       // 165
constexpr int KCP_ = 192;          // padded K for conv GEMM
constexpr int QS_  = 3 * D_;       // fused qkv row stride (1536)

// ---------------- scratch (static device allocations) ----------------------
__device__ float g_h   [BL_ * D_];
__device__ float g_qkv [BL_ * QS_];
__device__ float g_o   [BL_ * D_];
__device__ float g_y   [BL_ * DFF_];
__device__ float g_xg  [BL_ * KCP_];
__device__ float g_wp  [D_ * KCP_];
__device__ float g_wqkv[NL_ * QS_ * D_];
__device__ float g_bqkv[NL_ * QS_];

// ---------------- im2col gather (padded, zero-filled) -----------------------
__global__ void __launch_bounds__(256) gather_kernel(const float* __restrict__ x) {
    int idx = blockIdx.x * blockDim.x + threadIdx.x;
    const int total = BL_ * KCP_;
    if (idx >= total) return;
    int kk = idx % KCP_;
    int bl = idx / KCP_;
    float val = 0.f;
    if (kk < KC_) {
        int c = kk / 3, j = kk % 3;
        int b = bl / L_, l = bl % L_;
        int ls = l - 1 + j;
        if (ls < 0) ls += L_;
        if (ls >= L_) ls -= L_;
        val = x[((size_t)b * L_ + ls) * C_ + c];
    }
    g_xg[idx] = val;
}

__global__ void __launch_bounds__(256) packw_kernel(const float* __restrict__ w) {
    int idx = blockIdx.x * blockDim.x + threadIdx.x;
    const int total = D_ * KCP_;
    if (idx >= total) return;
    int kk = idx % KCP_;
    int r  = idx / KCP_;
    g_wp[idx] = (kk < KC_) ? w[(size_t)r * KC_ + kk] : 0.f;
}

// pack Wq/Wk/Wv -> [l][1536][512], bq/bk/bv -> [l][1536]
__global__ void __launch_bounds__(256) packqkv_kernel(
    const float* __restrict__ Wq, const float* __restrict__ Wk,
    const float* __restrict__ Wv,
    const float* __restrict__ bq, const float* __restrict__ bk,
    const float* __restrict__ bv)
{
    int idx = blockIdx.x * blockDim.x + threadIdx.x;
    const int perL = QS_ * D_;
    if (idx < NL_ * perL) {
        int l = idx / perL, rem = idx % perL;
        int row = rem / D_, col = rem % D_;
        const float* src = (row < D_) ? Wq : (row < 2 * D_) ? Wk : Wv;
        int r = row % D_;
        g_wqkv[idx] = src[((size_t)l * D_ + r) * D_ + col];
    }
    if (idx < NL_ * QS_) {
        int l = idx / QS_, row = idx % QS_;
        const float* src = (row < D_) ? bq : (row < 2 * D_) ? bk : bv;
        g_bqkv[idx] = src[(size_t)l * D_ + row % D_];
    }
}

// ---------------- bf16 hi/lo split helper -----------------------------------
__device__ __forceinline__ void split2(float x, float y,
                                       uint32_t& hi, uint32_t& lo) {
    __nv_bfloat16 hx = __float2bfloat16(x);
    __nv_bfloat16 hy = __float2bfloat16(y);
    float lx = x - __bfloat162float(hx);
    float ly = y - __bfloat162float(hy);
    __nv_bfloat16 gx = __float2bfloat16(lx);
    __nv_bfloat16 gy = __float2bfloat16(ly);
    hi = (uint32_t)__bfloat16_as_ushort(hx) |
         ((uint32_t)__bfloat16_as_ushort(hy) << 16);
    lo = (uint32_t)__bfloat16_as_ushort(gx) |
         ((uint32_t)__bfloat16_as_ushort(gy) << 16);
}

#define MMA_BF16(C, A0, A1, A2, A3, B0, B1)                                   \
    asm volatile(                                                             \
        "mma.sync.aligned.m16n8k16.row.col.f32.bf16.bf16.f32 "                \
        "{%0,%1,%2,%3}, {%4,%5,%6,%7}, {%8,%9}, {%0,%1,%2,%3};\n"             \
        : "+f"(C[0]), "+f"(C[1]), "+f"(C[2]), "+f"(C[3])                      \
        : "r"(A0), "r"(A1), "r"(A2), "r"(A3), "r"(B0), "r"(B1))

__device__ __forceinline__ void ldsm4(uint32_t& r0, uint32_t& r1,
                                      uint32_t& r2, uint32_t& r3,
                                      uint32_t addr) {
    asm volatile(
        "ldmatrix.sync.aligned.m8n8.x4.shared.b16 {%0,%1,%2,%3}, [%4];\n"
        : "=r"(r0), "=r"(r1), "=r"(r2), "=r"(r3) : "r"(addr));
}

// ---------------- bf16x2-split tensor-core GEMM (2 CTAs/SM) -----------------
// C [M,N] (+)= A[M,K] @ W[N,K]^T + bias, fp32 in/out, ~fp32 precision via
// hi/lo bf16 split (3 mma per k16).  MODE: 0 plain, 1 C+=, 2 GELU, 3 +PE.
// BM=128, BN=64, 8 warps, two CTAs co-resident per SM so one CTA's mma
// stream covers the other's store/sync bubble.
// NOTE (round-10 bug): B-side ldmatrix lane map MUST be the n8-within-16 /
// k16-half ordering below; reusing the A lane map permutes the k8-15 half
// of B against wrong n columns.
template<int MODE>
__global__ void __launch_bounds__(256, 2) mma_gemm(
    int M, int N, int K,
    const float* __restrict__ A,
    const float* __restrict__ W,
    const float* __restrict__ bias,
    float* __restrict__ Cp,
    const float* __restrict__ pe)
{
    constexpr int BM = 128, BN = 64, BK = 32;
    constexpr int WARPS_N = 2, WARPS_M = 4;
    constexpr int WM = BM / WARPS_M;         // 32
    constexpr int WN = BN / WARPS_N;         // 32
    constexpr int MT  = WM / 16;             // 2
    constexpr int NT2 = WN / 16;             // 2
    constexpr int ROWB   = 80;               // bytes per plane row (32 bf16 + pad)
    constexpr int STRW   = ROWB / 4;         // 20 words
    constexpr int A_BYTES = BM * ROWB;
    constexpr int B_BYTES = BN * ROWB;
    constexpr int STAGE_B = 2 * A_BYTES + 2 * B_BYTES;   // 30720 B
    constexpr int ALOADS = BM * BK / 4 / 256;   // 4
    constexpr int BLOADS = BN * BK / 4 / 256;   // 2

    extern __shared__ uint32_t smw[];
    const uint32_t smemBase = (uint32_t)__cvta_generic_to_shared(smw);

    const int tid  = threadIdx.x;
    const int warp = tid >> 5, lane = tid & 31;
    const int wm = (warp >> 1) * WM;
    const int wn = (warp & 1) * WN;
    const int g  = lane >> 2;
    const int tg = lane & 3;
    const int rowBase = blockIdx.y * BM;
    const int colBase = blockIdx.x * BN;

    // ldmatrix lane-derived address components
    // A tile (16x32 per x4): lanes 0-15 -> rows 0-15 @k-bytes 0,
    //                        lanes 16-31 -> rows 0-15 @k-bytes 16.
    const int aRow = lane & 15;
    const int aKB  = (lane >> 4) * 16;
    const uint32_t aOff = (uint32_t)((wm + aRow) * ROWB + aKB);
    // B tile: regs must come out {n0-7/k0-7, n0-7/k8-15, n8-15/k0-7, n8-15/k8-15}
    const int bRow = (lane & 7) | (((lane >> 4) & 1) << 3);
    const int bKB  = ((lane >> 3) & 1) * 16;
    const uint32_t bOff = (uint32_t)((wn + bRow) * ROWB + bKB);

    float c[MT][2 * NT2][4];
    #pragma unroll
    for (int mt = 0; mt < MT; ++mt)
        #pragma unroll
        for (int nt = 0; nt < 2 * NT2; ++nt)
            #pragma unroll
            for (int j = 0; j < 4; ++j) c[mt][nt][j] = 0.f;

    float4 aR[ALOADS], bR[BLOADS];

    auto loadG = [&](int k0) {
        #pragma unroll
        for (int i = 0; i < ALOADS; ++i) {
            int f = tid + i * 256;
            int r = f >> 3, cc = (f & 7) * 4;
            aR[i] = *reinterpret_cast<const float4*>(
                A + (size_t)(rowBase + r) * K + k0 + cc);
        }
        #pragma unroll
        for (int i = 0; i < BLOADS; ++i) {
            int f = tid + i * 256;
            int r = f >> 3, cc = (f & 7) * 4;
            int gr = colBase + r;
            bR[i] = (gr < N)
                ? *reinterpret_cast<const float4*>(W + (size_t)gr * K + k0 + cc)
                : make_float4(0.f, 0.f, 0.f, 0.f);
        }
    };

    auto storeS = [&](int s) {
        uint32_t* base = smw + s * (STAGE_B / 4);
        uint32_t* Ah = base;
        uint32_t* Al = Ah + A_BYTES / 4;
        uint32_t* Bh = Al + A_BYTES / 4;
        uint32_t* Bl = Bh + B_BYTES / 4;
        #pragma unroll
        for (int i = 0; i < ALOADS; ++i) {
            int f = tid + i * 256;
            int r = f >> 3, cw = (f & 7) * 2;
            uint32_t h0, l0, h1, l1;
            split2(aR[i].x, aR[i].y, h0, l0);
            split2(aR[i].z, aR[i].w, h1, l1);
            *reinterpret_cast<uint2*>(&Ah[r * STRW + cw]) = make_uint2(h0, h1);
            *reinterpret_cast<uint2*>(&Al[r * STRW + cw]) = make_uint2(l0, l1);
        }
        #pragma unroll
        for (int i = 0; i < BLOADS; ++i) {
            int f = tid + i * 256;
            int r = f >> 3, cw = (f & 7) * 2;
            uint32_t h0, l0, h1, l1;
            split2(bR[i].x, bR[i].y, h0, l0);
            split2(bR[i].z, bR[i].w, h1, l1);
            *reinterpret_cast<uint2*>(&Bh[r * STRW + cw]) = make_uint2(h0, h1);
            *reinterpret_cast<uint2*>(&Bl[r * STRW + cw]) = make_uint2(l0, l1);
        }
    };

    auto compute = [&](int s) {
        const uint32_t stage = smemBase + (uint32_t)(s * STAGE_B);
        const uint32_t AhB = stage + aOff;
        const uint32_t AlB = AhB + A_BYTES;
        const uint32_t BhB = stage + 2 * A_BYTES + bOff;
        const uint32_t BlB = BhB + B_BYTES;
        #pragma unroll
        for (int ks = 0; ks < 2; ++ks) {
            const uint32_t kOfs = ks * 32;
            uint32_t ah[MT][4], al[MT][4], bh[NT2][4], bl[NT2][4];
            #pragma unroll
            for (int mt = 0; mt < MT; ++mt) {
                ldsm4(ah[mt][0], ah[mt][1], ah[mt][2], ah[mt][3],
                      AhB + mt * 16 * ROWB + kOfs);
                ldsm4(al[mt][0], al[mt][1], al[mt][2], al[mt][3],
                      AlB + mt * 16 * ROWB + kOfs);
            }
            #pragma unroll
            for (int n2 = 0; n2 < NT2; ++n2) {
                ldsm4(bh[n2][0], bh[n2][1], bh[n2][2], bh[n2][3],
                      BhB + n2 * 16 * ROWB + kOfs);
                ldsm4(bl[n2][0], bl[n2][1], bl[n2][2], bl[n2][3],
                      BlB + n2 * 16 * ROWB + kOfs);
            }
            #pragma unroll
            for (int mt = 0; mt < MT; ++mt)
                #pragma unroll
                for (int n2 = 0; n2 < NT2; ++n2)
                    #pragma unroll
                    for (int half = 0; half < 2; ++half) {
                        float* cc = c[mt][n2 * 2 + half];
                        uint32_t b0h = bh[n2][half * 2],
                                 b1h = bh[n2][half * 2 + 1];
                        uint32_t b0l = bl[n2][half * 2],
                                 b1l = bl[n2][half * 2 + 1];
                        MMA_BF16(cc, ah[mt][0], ah[mt][1], ah[mt][2],
                                 ah[mt][3], b0h, b1h);
                        MMA_BF16(cc, ah[mt][0], ah[mt][1], ah[mt][2],
                                 ah[mt][3], b0l, b1l);
                        MMA_BF16(cc, al[mt][0], al[mt][1], al[mt][2],
                                 al[mt][3], b0h, b1h);
                    }
        }
    };

    const int nIter = K / BK;
    int s = 0;
    loadG(0);
    storeS(0);
    __syncthreads();
    for (int it = 0; it < nIter; ++it) {
        const bool more = (it + 1 < nIter);
        if (more) loadG((it + 1) * BK);
        compute(s);
        if (more) storeS(s ^ 1);
        __syncthreads();
        s ^= 1;
    }

    // epilogue
    #pragma unroll
    for (int mt = 0; mt < MT; ++mt) {
        #pragma unroll
        for (int nt = 0; nt < 2 * NT2; ++nt) {
            int r0 = rowBase + wm + mt * 16 + g;
            int c0 = colBase + wn + nt * 8 + tg * 2;
            #pragma unroll
            for (int half = 0; half < 2; ++half) {
                int r = r0 + half * 8;
                #pragma unroll
                for (int jj = 0; jj < 2; ++jj) {
                    int cc = c0 + jj;
                    if (cc >= N) continue;
                    float v = c[mt][nt][half * 2 + jj];
                    if (bias) v += bias[cc];
                    if (MODE == 3) v += pe[(size_t)(r % L_) * N + cc];
                    if (MODE == 2) v = 0.5f * v * (1.f + erff(v * 0.70710678118654752f));
                    size_t off = (size_t)r * N + cc;
                    if (MODE == 1) v += Cp[off];
                    Cp[off] = v;
                }
            }
        }
    }
}

// ---------------- attention: one CTA per (b, h) -----------------------------
constexpr int S_STRIDE = 104;
constexpr int ATTN_SMEM_FLOATS = L_ * S_STRIDE + L_ * DK_ + DK_ * L_;
constexpr int ATTN_SMEM_BYTES  = ATTN_SMEM_FLOATS * 4;   // 92800 B

__global__ void __launch_bounds__(256) attn_kernel(
    const float* __restrict__ qkv,   // [BL][1536]: q|k|v
    float* __restrict__ o)           // [BL][512]
{
    extern __shared__ float sm[];
    float* S   = sm;                          // [100][104]
    float* qs  = sm + L_ * S_STRIDE;          // [100][64]
    float* kst = qs + L_ * DK_;               // [64][100] (reused for v)

    const int b = blockIdx.x / H_;
    const int h = blockIdx.x % H_;
    const float* qb = qkv + ((size_t)b * L_) * QS_ + h * DK_;
    const float* kb = qb + D_;
    const float* vb = qb + 2 * D_;
    float*       ob = o + ((size_t)b * L_) * D_ + h * DK_;
    const int tid = threadIdx.x;

    for (int idx = tid; idx < L_ * DK_; idx += blockDim.x) {
        int r = idx / DK_, e = idx % DK_;
        qs [r * DK_ + e] = qb[(size_t)r * QS_ + e];
        kst[e * L_  + r] = kb[(size_t)r * QS_ + e];
    }
    __syncthreads();

    const float scale = 0.125f;
    for (int p = tid; p < L_ * (L_ / 4); p += blockDim.x) {
        int i  = p / (L_ / 4);
        int j4 = (p % (L_ / 4)) * 4;
        float s0 = 0.f, s1 = 0.f, s2 = 0.f, s3 = 0.f;
        #pragma unroll 8
        for (int e = 0; e < DK_; ++e) {
            float qv = qs[i * DK_ + e];
            const float4 kv = *reinterpret_cast<const float4*>(kst + e * L_ + j4);
            s0 = fmaf(qv, kv.x, s0);
            s1 = fmaf(qv, kv.y, s1);
            s2 = fmaf(qv, kv.z, s2);
            s3 = fmaf(qv, kv.w, s3);
        }
        *reinterpret_cast<float4*>(S + i * S_STRIDE + j4) =
            make_float4(s0 * scale, s1 * scale, s2 * scale, s3 * scale);
    }
    __syncthreads();

    float* vs = kst;
    for (int idx = tid; idx < L_ * DK_; idx += blockDim.x) {
        int r = idx / DK_, e = idx % DK_;
        vs[r * DK_ + e] = vb[(size_t)r * QS_ + e];
    }
    {
        int warp = tid >> 5, lane = tid & 31;
        for (int i = warp; i < L_; i += (int)(blockDim.x >> 5)) {
            float* Sr = S + i * S_STRIDE;
            float m = -1e30f;
            for (int j = lane; j < L_; j += 32) m = fmaxf(m, Sr[j]);
            #pragma unroll
            for (int off = 16; off; off >>= 1)
                m = fmaxf(m, __shfl_xor_sync(0xffffffff, m, off));
            float sum = 0.f;
            for (int j = lane; j < L_; j += 32) {
                float ev = __expf(Sr[j] - m);
                Sr[j] = ev;
                sum += ev;
            }
            #pragma unroll
            for (int off = 16; off; off >>= 1)
                sum += __shfl_xor_sync(0xffffffff, sum, off);
            float inv = 1.f / sum;
            for (int j = lane; j < L_; j += 32) Sr[j] *= inv;
        }
    }
    __syncthreads();

    for (int idx = tid; idx < L_ * DK_; idx += blockDim.x) {
        int i = idx / DK_, d = idx % DK_;
        const float* Sr = S + i * S_STRIDE;
        float a0 = 0.f, a1 = 0.f, a2 = 0.f, a3 = 0.f;
        #pragma unroll 4
        for (int j = 0; j < L_; j += 4) {
            a0 = fmaf(Sr[j    ], vs[(j    ) * DK_ + d], a0);
            a1 = fmaf(Sr[j + 1], vs[(j + 1) * DK_ + d], a1);
            a2 = fmaf(Sr[j + 2], vs[(j + 2) * DK_ + d], a2);
            a3 = fmaf(Sr[j + 3], vs[(j + 3) * DK_ + d], a3);
        }
        ob[(size_t)i * D_ + d] = (a0 + a1) + (a2 + a3);
    }
}

// ---------------- host-side launch helper -----------------------------------
template<int MODE>
static void launch_one(const float* A, const float* W, const float* bias,
                       float* C, int M, int N, int K, const float* pe) {
    constexpr int STAGE_B = (2 * 128 + 2 * 64) * 80;  // 30720 bytes per stage
    constexpr int SMEM = 2 * STAGE_B;                 // 61440
    static bool done = false;
    if (!done) {
        cudaFuncSetAttribute(mma_gemm<MODE>,
                             cudaFuncAttributeMaxDynamicSharedMemorySize, SMEM);
        done = true;
    }
    dim3 grid((N + 63) / 64, M / 128);
    mma_gemm<MODE><<<grid, 256, SMEM>>>(M, N, K, A, W, bias, C, pe);
}

static void mgemm(const float* A, const float* W, const float* bias, float* C,
                  int M, int N, int K, int mode, const float* pe = nullptr) {
    switch (mode) {
        case 0: launch_one<0>(A, W, bias, C, M, N, K, nullptr); break;
        case 1: launch_one<1>(A, W, bias, C, M, N, K, nullptr); break;
        case 2: launch_one<2>(A, W, bias, C, M, N, K, nullptr); break;
        default: launch_one<3>(A, W, bias, C, M, N, K, pe);     break;
    }
}

extern "C" void kernel_launch(void* const* d_in, const int* in_sizes, int n_in,
                              void* d_out, int out_size) {
    (void)in_sizes; (void)n_in; (void)out_size;
    const float* x     = (const float*)d_in[0];
    const float* tok_w = (const float*)d_in[1];
    const float* pe    = (const float*)d_in[2];
    const float* Wq    = (const float*)d_in[3];
    const float* bq    = (const float*)d_in[4];
    const float* Wk    = (const float*)d_in[5];
    const float* bk    = (const float*)d_in[6];
    const float* Wv    = (const float*)d_in[7];
    const float* bv    = (const float*)d_in[8];
    // d_in[9]/d_in[10] (Wsig/bsig): prior branch never reaches output -> skipped
    const float* Wo    = (const float*)d_in[11];
    const float* bo    = (const float*)d_in[12];
    const float* W1    = (const float*)d_in[13];
    const float* b1    = (const float*)d_in[14];
    const float* W2    = (const float*)d_in[15];
    const float* b2    = (const float*)d_in[16];
    const float* pw    = (const float*)d_in[17];
    const float* pb    = (const float*)d_in[18];
    float* out = (float*)d_out;

    float *h, *qkv, *o, *y, *xg, *wp, *wqkv, *bqkv;
    cudaGetSymbolAddress((void**)&h,    g_h);
    cudaGetSymbolAddress((void**)&qkv,  g_qkv);
    cudaGetSymbolAddress((void**)&o,    g_o);
    cudaGetSymbolAddress((void**)&y,    g_y);
    cudaGetSymbolAddress((void**)&xg,   g_xg);
    cudaGetSymbolAddress((void**)&wp,   g_wp);
    cudaGetSymbolAddress((void**)&wqkv, g_wqkv);
    cudaGetSymbolAddress((void**)&bqkv, g_bqkv);

    cudaFuncSetAttribute(attn_kernel,
                         cudaFuncAttributeMaxDynamicSharedMemorySize,
                         ATTN_SMEM_BYTES);

    // prep: padded im2col, padded tok_w, fused qkv weights
    gather_kernel<<<(BL_ * KCP_ + 255) / 256, 256>>>(x);
    packw_kernel<<<(D_ * KCP_ + 255) / 256, 256>>>(tok_w);
    packqkv_kernel<<<(NL_ * QS_ * D_ + 255) / 256, 256>>>(Wq, Wk, Wv, bq, bk, bv);

    // token embedding GEMM (+positional-embedding epilogue)
    mgemm(xg, wp, nullptr, h, BL_, D_, KCP_, 3, pe);

    for (int l = 0; l < NL_; ++l) {
        const size_t wOff = (size_t)l * D_ * D_;
        // fused QKV projection: [BL,512] @ [1536,512]^T
        mgemm(h, wqkv + (size_t)l * QS_ * D_, bqkv + (size_t)l * QS_,
              qkv, BL_, QS_, D_, 0);

        attn_kernel<<<B_ * H_, 256, ATTN_SMEM_BYTES>>>(qkv, o);

        mgemm(o, Wo + wOff, bo + (size_t)l * D_, h, BL_, D_, D_, 1);
        mgemm(h, W1 + (size_t)l * DFF_ * D_, b1 + (size_t)l * DFF_,
              y, BL_, DFF_, D_, 2);
        mgemm(y, W2 + (size_t)l * D_ * DFF_, b2 + (size_t)l * D_,
              h, BL_, D_, DFF_, 1);
    }

    mgemm(h, pw, pb, out, BL_, C_, D_, 0);
}

// round 13
// speedup vs baseline: 1.4746x; 1.4746x over previous
#include <cuda_runtime.h>
#include <cuda_bf16.h>
#include <math.h>
#include <stdint.h>

// Problem constants
constexpr int B_   = 256;
constexpr int L_   = 100;
constexpr int C_   = 55;
constexpr int D_   = 512;
constexpr int H_   = 8;
constexpr int NL_  = 3;
constexpr int DFF_ = 64;
constexpr int DK_  = D_ / H_;      // 64
constexpr int BL_  = B_ * L_;      // 25600
constexpr int KC_  = 3 * C_;       // 165
constexpr int KCP_ = 192;          // padded K for conv GEMM
constexpr int QS_  = 3 * D_;       // fused qkv row stride (1536)

typedef __nv_bfloat16 bf16;

// ---------------- scratch (static device allocations) ----------------------
__device__ float g_h   [BL_ * D_];      // fp32 residual stream
__device__ float g_qkv [BL_ * QS_];     // fp32 (attention input)
__device__ float g_bqkv[NL_ * QS_];
// bf16 hi/lo planes (GEMM operands)
__device__ bf16 g_h_hi [BL_ * D_],   g_h_lo [BL_ * D_];
__device__ bf16 g_o_hi [BL_ * D_],   g_o_lo [BL_ * D_];
__device__ bf16 g_y_hi [BL_ * DFF_], g_y_lo [BL_ * DFF_];
__device__ bf16 g_xg_hi[BL_ * KCP_], g_xg_lo[BL_ * KCP_];
__device__ bf16 g_wp_hi[D_ * KCP_],  g_wp_lo[D_ * KCP_];
__device__ bf16 g_wqkv_hi[NL_ * QS_ * D_], g_wqkv_lo[NL_ * QS_ * D_];
__device__ bf16 g_wo_hi[NL_ * D_ * D_],    g_wo_lo[NL_ * D_ * D_];
__device__ bf16 g_w1_hi[NL_ * DFF_ * D_],  g_w1_lo[NL_ * DFF_ * D_];
__device__ bf16 g_w2_hi[NL_ * D_ * DFF_],  g_w2_lo[NL_ * D_ * DFF_];
__device__ bf16 g_pw_hi[C_ * D_],          g_pw_lo[C_ * D_];

// ---------------- split helpers ---------------------------------------------
__device__ __forceinline__ void splitE(float v, bf16& h, bf16& l) {
    h = __float2bfloat16(v);
    l = __float2bfloat16(v - __bfloat162float(h));
}

// ---------------- im2col gather -> hi/lo planes ------------------------------
__global__ void __launch_bounds__(256) gather_kernel(const float* __restrict__ x) {
    int idx = blockIdx.x * blockDim.x + threadIdx.x;
    const int total = BL_ * KCP_;
    if (idx >= total) return;
    int kk = idx % KCP_;
    int bl = idx / KCP_;
    float val = 0.f;
    if (kk < KC_) {
        int c = kk / 3, j = kk % 3;
        int b = bl / L_, l = bl % L_;
        int ls = l - 1 + j;
        if (ls < 0) ls += L_;
        if (ls >= L_) ls -= L_;
        val = x[((size_t)b * L_ + ls) * C_ + c];
    }
    splitE(val, g_xg_hi[idx], g_xg_lo[idx]);
}

// pack tok_w [D][165] -> hilo [D][192]
__global__ void __launch_bounds__(256) packw_kernel(const float* __restrict__ w) {
    int idx = blockIdx.x * blockDim.x + threadIdx.x;
    const int total = D_ * KCP_;
    if (idx >= total) return;
    int kk = idx % KCP_;
    int r  = idx / KCP_;
    float v = (kk < KC_) ? w[(size_t)r * KC_ + kk] : 0.f;
    splitE(v, g_wp_hi[idx], g_wp_lo[idx]);
}

// pack Wq/Wk/Wv -> hilo [l][1536][512], biases -> fp32 [l][1536]
__global__ void __launch_bounds__(256) packqkv_kernel(
    const float* __restrict__ Wq, const float* __restrict__ Wk,
    const float* __restrict__ Wv,
    const float* __restrict__ bq, const float* __restrict__ bk,
    const float* __restrict__ bv)
{
    int idx = blockIdx.x * blockDim.x + threadIdx.x;
    const int perL = QS_ * D_;
    if (idx < NL_ * perL) {
        int l = idx / perL, rem = idx % perL;
        int row = rem / D_, col = rem % D_;
        const float* src = (row < D_) ? Wq : (row < 2 * D_) ? Wk : Wv;
        int r = row % D_;
        splitE(src[((size_t)l * D_ + r) * D_ + col], g_wqkv_hi[idx], g_wqkv_lo[idx]);
    }
    if (idx < NL_ * QS_) {
        int l = idx / QS_, row = idx % QS_;
        const float* src = (row < D_) ? bq : (row < 2 * D_) ? bk : bv;
        g_bqkv[idx] = src[(size_t)l * D_ + row % D_];
    }
}

// generic fp32 -> hilo
__global__ void __launch_bounds__(256) f2hl_kernel(
    const float* __restrict__ in, bf16* __restrict__ hi, bf16* __restrict__ lo,
    int n)
{
    int i = blockIdx.x * blockDim.x + threadIdx.x;
    if (i >= n) return;
    splitE(in[i], hi[i], lo[i]);
}

// ---------------- mma / ldmatrix helpers ------------------------------------
#define MMA_BF16(C, A0, A1, A2, A3, B0, B1)                                   \
    asm volatile(                                                             \
        "mma.sync.aligned.m16n8k16.row.col.f32.bf16.bf16.f32 "                \
        "{%0,%1,%2,%3}, {%4,%5,%6,%7}, {%8,%9}, {%0,%1,%2,%3};\n"             \
        : "+f"(C[0]), "+f"(C[1]), "+f"(C[2]), "+f"(C[3])                      \
        : "r"(A0), "r"(A1), "r"(A2), "r"(A3), "r"(B0), "r"(B1))

__device__ __forceinline__ void ldsm4(uint32_t& r0, uint32_t& r1,
                                      uint32_t& r2, uint32_t& r3,
                                      uint32_t addr) {
    asm volatile(
        "ldmatrix.sync.aligned.m8n8.x4.shared.b16 {%0,%1,%2,%3}, [%4];\n"
        : "=r"(r0), "=r"(r1), "=r"(r2), "=r"(r3) : "r"(addr));
}

#define CP16(dst, src)                                                        \
    asm volatile("cp.async.ca.shared.global [%0], [%1], 16;\n"                \
                 :: "r"(dst), "l"(src))
#define CP16Z(dst, src, nbytes)                                               \
    asm volatile("cp.async.ca.shared.global [%0], [%1], 16, %2;\n"            \
                 :: "r"(dst), "l"(src), "r"(nbytes))

// ---------------- bf16-split tensor-core GEMM, cp.async 4-stage -------------
// C [M,N] (+)= A[M,K] @ W[N,K]^T + bias, operands are pre-split bf16 hi/lo
// planes in GMEM; 3-term product (AhBh + AhBl + AlBh) ~ fp32 precision.
// MODE: 0 fp32 out only; 1 C += v, write fp32 + hilo; 2 GELU, write hilo
// only; 3 +PE, write fp32 + hilo.  Requires M%128==0, K%32==0.
template<int MODE>
__global__ void __launch_bounds__(256) mma_gemm(
    int M, int N, int K,
    const bf16* __restrict__ Agh, const bf16* __restrict__ Agl,
    const bf16* __restrict__ Bgh, const bf16* __restrict__ Bgl,
    const float* __restrict__ bias,
    float* __restrict__ Cp,
    bf16* __restrict__ Oh, bf16* __restrict__ Ol,
    const float* __restrict__ pe)
{
    constexpr int BM = 128, BN = 128, BK = 32;
    constexpr int WM = 64, WN = 32;          // 2x4 warp grid
    constexpr int MT  = WM / 16;             // 4
    constexpr int NT2 = WN / 16;             // 2
    constexpr int ROWB    = 80;              // 64B data + 16B pad per row
    constexpr int PLANE_B = BM * ROWB;       // 10240 (A and B tiles same size)
    constexpr int STAGE_B = 4 * PLANE_B;     // Ah|Al|Bh|Bl = 40960
    constexpr int STAGES  = 4;

    extern __shared__ uint32_t smw[];
    const uint32_t smemBase = (uint32_t)__cvta_generic_to_shared(smw);

    const int tid  = threadIdx.x;
    const int warp = tid >> 5, lane = tid & 31;
    const int wm = (warp >> 2) * WM;         // warp/4 in {0,1}
    const int wn = (warp & 3) * WN;          // warp%4 in {0..3}
    const int g  = lane >> 2;
    const int tg = lane & 3;
    const int rowBase = blockIdx.y * BM;
    const int colBase = blockIdx.x * BN;

    // ldmatrix lane maps (proven in rounds 7/11/12):
    const int aRow = lane & 15;
    const int aKB  = (lane >> 4) * 16;
    const uint32_t aOff = (uint32_t)((wm + aRow) * ROWB + aKB);
    const int bRow = (lane & 7) | (((lane >> 4) & 1) << 3);
    const int bKB  = ((lane >> 3) & 1) * 16;
    const uint32_t bOff = (uint32_t)((wn + bRow) * ROWB + bKB);

    float c[MT][2 * NT2][4];
    #pragma unroll
    for (int mt = 0; mt < MT; ++mt)
        #pragma unroll
        for (int nt = 0; nt < 2 * NT2; ++nt)
            #pragma unroll
            for (int j = 0; j < 4; ++j) c[mt][nt][j] = 0.f;

    auto loadStage = [&](int st, int k0) {
        const uint32_t sa = smemBase + (uint32_t)(st * STAGE_B);
        // A planes: 128 rows x 4 chunks of 16B, 512 chunks per plane
        #pragma unroll
        for (int i = 0; i < 2; ++i) {
            int f = tid + i * 256;           // 0..511
            int r = f >> 2, ch = f & 3;
            uint32_t d = sa + (uint32_t)(r * ROWB + ch * 16);
            size_t go = (size_t)(rowBase + r) * K + k0 + ch * 8;
            CP16(d, Agh + go);
            CP16(d + PLANE_B, Agl + go);
        }
        // B planes with n-guard (zero-fill rows >= N)
        #pragma unroll
        for (int i = 0; i < 2; ++i) {
            int f = tid + i * 256;
            int r = f >> 2, ch = f & 3;
            int gr = colBase + r;
            int nb = (gr < N) ? 16 : 0;
            int grc = (gr < N) ? gr : (N - 1);
            uint32_t d = sa + (uint32_t)(2 * PLANE_B + r * ROWB + ch * 16);
            size_t go = (size_t)grc * K + k0 + ch * 8;
            CP16Z(d, Bgh + go, nb);
            CP16Z(d + PLANE_B, Bgl + go, nb);
        }
    };

    auto compute = [&](int st) {
        const uint32_t stage = smemBase + (uint32_t)(st * STAGE_B);
        const uint32_t AhB = stage + aOff;
        const uint32_t AlB = AhB + PLANE_B;
        const uint32_t BhB = stage + 2 * PLANE_B + bOff;
        const uint32_t BlB = BhB + PLANE_B;
        #pragma unroll
        for (int ks = 0; ks < 2; ++ks) {
            const uint32_t kOfs = ks * 32;
            uint32_t ah[MT][4], al[MT][4], bh[NT2][4], bl[NT2][4];
            #pragma unroll
            for (int mt = 0; mt < MT; ++mt) {
                ldsm4(ah[mt][0], ah[mt][1], ah[mt][2], ah[mt][3],
                      AhB + mt * 16 * ROWB + kOfs);
                ldsm4(al[mt][0], al[mt][1], al[mt][2], al[mt][3],
                      AlB + mt * 16 * ROWB + kOfs);
            }
            #pragma unroll
            for (int n2 = 0; n2 < NT2; ++n2) {
                ldsm4(bh[n2][0], bh[n2][1], bh[n2][2], bh[n2][3],
                      BhB + n2 * 16 * ROWB + kOfs);
                ldsm4(bl[n2][0], bl[n2][1], bl[n2][2], bl[n2][3],
                      BlB + n2 * 16 * ROWB + kOfs);
            }
            #pragma unroll
            for (int mt = 0; mt < MT; ++mt)
                #pragma unroll
                for (int n2 = 0; n2 < NT2; ++n2)
                    #pragma unroll
                    for (int half = 0; half < 2; ++half) {
                        float* cc = c[mt][n2 * 2 + half];
                        uint32_t b0h = bh[n2][half * 2],
                                 b1h = bh[n2][half * 2 + 1];
                        uint32_t b0l = bl[n2][half * 2],
                                 b1l = bl[n2][half * 2 + 1];
                        MMA_BF16(cc, ah[mt][0], ah[mt][1], ah[mt][2],
                                 ah[mt][3], b0h, b1h);
                        MMA_BF16(cc, ah[mt][0], ah[mt][1], ah[mt][2],
                                 ah[mt][3], b0l, b1l);
                        MMA_BF16(cc, al[mt][0], al[mt][1], al[mt][2],
                                 al[mt][3], b0h, b1h);
                    }
        }
    };

    const int nIter = K / BK;
    // prologue: prefetch STAGES-1 stages
    for (int st = 0; st < STAGES - 1; ++st) {
        if (st < nIter) loadStage(st, st * BK);
        asm volatile("cp.async.commit_group;\n");
    }
    for (int it = 0; it < nIter; ++it) {
        asm volatile("cp.async.wait_group %0;\n" :: "n"(STAGES - 2));
        __syncthreads();
        compute(it % STAGES);
        int pi = it + STAGES - 1;
        if (pi < nIter) loadStage(pi % STAGES, pi * BK);
        asm volatile("cp.async.commit_group;\n");
    }

    // epilogue
    #pragma unroll
    for (int mt = 0; mt < MT; ++mt) {
        #pragma unroll
        for (int nt = 0; nt < 2 * NT2; ++nt) {
            int r0 = rowBase + wm + mt * 16 + g;
            int c0 = colBase + wn + nt * 8 + tg * 2;
            #pragma unroll
            for (int half = 0; half < 2; ++half) {
                int r = r0 + half * 8;
                if (c0 + 1 < N) {
                    float v0 = c[mt][nt][half * 2 + 0];
                    float v1 = c[mt][nt][half * 2 + 1];
                    if (bias) { v0 += bias[c0]; v1 += bias[c0 + 1]; }
                    if (MODE == 3) {
                        const float* per = pe + (size_t)(r % L_) * N;
                        v0 += per[c0]; v1 += per[c0 + 1];
                    }
                    if (MODE == 2) {
                        v0 = 0.5f * v0 * (1.f + erff(v0 * 0.70710678118654752f));
                        v1 = 0.5f * v1 * (1.f + erff(v1 * 0.70710678118654752f));
                    }
                    size_t off = (size_t)r * N + c0;
                    if (MODE == 1) {
                        v0 += Cp[off]; v1 += Cp[off + 1];
                    }
                    if (MODE != 2) {
                        Cp[off] = v0; Cp[off + 1] = v1;
                    }
                    if (MODE == 1 || MODE == 2 || MODE == 3) {
                        bf16 h0, l0, h1, l1;
                        splitE(v0, h0, l0);
                        splitE(v1, h1, l1);
                        Oh[off] = h0; Oh[off + 1] = h1;
                        Ol[off] = l0; Ol[off + 1] = l1;
                    }
                } else if (c0 < N) {   // single-column tail (N=55 proj)
                    float v0 = c[mt][nt][half * 2 + 0];
                    if (bias) v0 += bias[c0];
                    size_t off = (size_t)r * N + c0;
                    if (MODE != 2) Cp[off] = v0;
                }
            }
        }
    }
}

// ---------------- attention: one CTA per (b, h), writes o hilo ---------------
constexpr int S_STRIDE = 104;
constexpr int ATTN_SMEM_FLOATS = L_ * S_STRIDE + L_ * DK_ + DK_ * L_;
constexpr int ATTN_SMEM_BYTES  = ATTN_SMEM_FLOATS * 4;   // 92800 B

__global__ void __launch_bounds__(256) attn_kernel(
    const float* __restrict__ qkv,   // [BL][1536]: q|k|v
    bf16* __restrict__ ohp, bf16* __restrict__ olp)
{
    extern __shared__ float sm[];
    float* S   = sm;                          // [100][104]
    float* qs  = sm + L_ * S_STRIDE;          // [100][64]
    float* kst = qs + L_ * DK_;               // [64][100] (reused for v)

    const int b = blockIdx.x / H_;
    const int h = blockIdx.x % H_;
    const float* qb = qkv + ((size_t)b * L_) * QS_ + h * DK_;
    const float* kb = qb + D_;
    const float* vb = qb + 2 * D_;
    bf16* obh = ohp + ((size_t)b * L_) * D_ + h * DK_;
    bf16* obl = olp + ((size_t)b * L_) * D_ + h * DK_;
    const int tid = threadIdx.x;

    for (int idx = tid; idx < L_ * DK_; idx += blockDim.x) {
        int r = idx / DK_, e = idx % DK_;
        qs [r * DK_ + e] = qb[(size_t)r * QS_ + e];
        kst[e * L_  + r] = kb[(size_t)r * QS_ + e];
    }
    __syncthreads();

    const float scale = 0.125f;
    for (int p = tid; p < L_ * (L_ / 4); p += blockDim.x) {
        int i  = p / (L_ / 4);
        int j4 = (p % (L_ / 4)) * 4;
        float s0 = 0.f, s1 = 0.f, s2 = 0.f, s3 = 0.f;
        #pragma unroll 8
        for (int e = 0; e < DK_; ++e) {
            float qv = qs[i * DK_ + e];
            const float4 kv = *reinterpret_cast<const float4*>(kst + e * L_ + j4);
            s0 = fmaf(qv, kv.x, s0);
            s1 = fmaf(qv, kv.y, s1);
            s2 = fmaf(qv, kv.z, s2);
            s3 = fmaf(qv, kv.w, s3);
        }
        *reinterpret_cast<float4*>(S + i * S_STRIDE + j4) =
            make_float4(s0 * scale, s1 * scale, s2 * scale, s3 * scale);
    }
    __syncthreads();

    float* vs = kst;
    for (int idx = tid; idx < L_ * DK_; idx += blockDim.x) {
        int r = idx / DK_, e = idx % DK_;
        vs[r * DK_ + e] = vb[(size_t)r * QS_ + e];
    }
    {
        int warp = tid >> 5, lane = tid & 31;
        for (int i = warp; i < L_; i += (int)(blockDim.x >> 5)) {
            float* Sr = S + i * S_STRIDE;
            float m = -1e30f;
            for (int j = lane; j < L_; j += 32) m = fmaxf(m, Sr[j]);
            #pragma unroll
            for (int off = 16; off; off >>= 1)
                m = fmaxf(m, __shfl_xor_sync(0xffffffff, m, off));
            float sum = 0.f;
            for (int j = lane; j < L_; j += 32) {
                float ev = __expf(Sr[j] - m);
                Sr[j] = ev;
                sum += ev;
            }
            #pragma unroll
            for (int off = 16; off; off >>= 1)
                sum += __shfl_xor_sync(0xffffffff, sum, off);
            float inv = 1.f / sum;
            for (int j = lane; j < L_; j += 32) Sr[j] *= inv;
        }
    }
    __syncthreads();

    for (int idx = tid; idx < L_ * DK_; idx += blockDim.x) {
        int i = idx / DK_, d = idx % DK_;
        const float* Sr = S + i * S_STRIDE;
        float a0 = 0.f, a1 = 0.f, a2 = 0.f, a3 = 0.f;
        #pragma unroll 4
        for (int j = 0; j < L_; j += 4) {
            a0 = fmaf(Sr[j    ], vs[(j    ) * DK_ + d], a0);
            a1 = fmaf(Sr[j + 1], vs[(j + 1) * DK_ + d], a1);
            a2 = fmaf(Sr[j + 2], vs[(j + 2) * DK_ + d], a2);
            a3 = fmaf(Sr[j + 3], vs[(j + 3) * DK_ + d], a3);
        }
        float v = (a0 + a1) + (a2 + a3);
        bf16 hh, ll;
        splitE(v, hh, ll);
        obh[(size_t)i * D_ + d] = hh;
        obl[(size_t)i * D_ + d] = ll;
    }
}

// ---------------- host-side launch helper -----------------------------------
template<int MODE>
static void launch_one(const bf16* Ah, const bf16* Al,
                       const bf16* Bh, const bf16* Bl,
                       const float* bias, float* C,
                       bf16* Oh, bf16* Ol,
                       int M, int N, int K, const float* pe) {
    constexpr int SMEM = 4 * 40960;   // 4 stages x 40 KB
    static bool done = false;
    if (!done) {
        cudaFuncSetAttribute(mma_gemm<MODE>,
                             cudaFuncAttributeMaxDynamicSharedMemorySize, SMEM);
        done = true;
    }
    dim3 grid((N + 127) / 128, M / 128);
    mma_gemm<MODE><<<grid, 256, SMEM>>>(M, N, K, Ah, Al, Bh, Bl,
                                        bias, C, Oh, Ol, pe);
}

extern "C" void kernel_launch(void* const* d_in, const int* in_sizes, int n_in,
                              void* d_out, int out_size) {
    (void)in_sizes; (void)n_in; (void)out_size;
    const float* x     = (const float*)d_in[0];
    const float* tok_w = (const float*)d_in[1];
    const float* pe    = (const float*)d_in[2];
    const float* Wq    = (const float*)d_in[3];
    const float* bq    = (const float*)d_in[4];
    const float* Wk    = (const float*)d_in[5];
    const float* bk    = (const float*)d_in[6];
    const float* Wv    = (const float*)d_in[7];
    const float* bv    = (const float*)d_in[8];
    // d_in[9]/d_in[10] (Wsig/bsig): prior branch never reaches output -> skipped
    const float* Wo    = (const float*)d_in[11];
    const float* bo    = (const float*)d_in[12];
    const float* W1    = (const float*)d_in[13];
    const float* b1    = (const float*)d_in[14];
    const float* W2    = (const float*)d_in[15];
    const float* b2    = (const float*)d_in[16];
    const float* pw    = (const float*)d_in[17];
    const float* pb    = (const float*)d_in[18];
    float* out = (float*)d_out;

    float *h, *qkv, *bqkv;
    bf16 *h_hi, *h_lo, *o_hi, *o_lo, *y_hi, *y_lo, *xg_hi, *xg_lo;
    bf16 *wp_hi, *wp_lo, *wqkv_hi, *wqkv_lo, *wo_hi, *wo_lo;
    bf16 *w1_hi, *w1_lo, *w2_hi, *w2_lo, *pw_hi, *pw_lo;
    cudaGetSymbolAddress((void**)&h,    g_h);
    cudaGetSymbolAddress((void**)&qkv,  g_qkv);
    cudaGetSymbolAddress((void**)&bqkv, g_bqkv);
    cudaGetSymbolAddress((void**)&h_hi, g_h_hi);   cudaGetSymbolAddress((void**)&h_lo, g_h_lo);
    cudaGetSymbolAddress((void**)&o_hi, g_o_hi);   cudaGetSymbolAddress((void**)&o_lo, g_o_lo);
    cudaGetSymbolAddress((void**)&y_hi, g_y_hi);   cudaGetSymbolAddress((void**)&y_lo, g_y_lo);
    cudaGetSymbolAddress((void**)&xg_hi, g_xg_hi); cudaGetSymbolAddress((void**)&xg_lo, g_xg_lo);
    cudaGetSymbolAddress((void**)&wp_hi, g_wp_hi); cudaGetSymbolAddress((void**)&wp_lo, g_wp_lo);
    cudaGetSymbolAddress((void**)&wqkv_hi, g_wqkv_hi); cudaGetSymbolAddress((void**)&wqkv_lo, g_wqkv_lo);
    cudaGetSymbolAddress((void**)&wo_hi, g_wo_hi); cudaGetSymbolAddress((void**)&wo_lo, g_wo_lo);
    cudaGetSymbolAddress((void**)&w1_hi, g_w1_hi); cudaGetSymbolAddress((void**)&w1_lo, g_w1_lo);
    cudaGetSymbolAddress((void**)&w2_hi, g_w2_hi); cudaGetSymbolAddress((void**)&w2_lo, g_w2_lo);
    cudaGetSymbolAddress((void**)&pw_hi, g_pw_hi); cudaGetSymbolAddress((void**)&pw_lo, g_pw_lo);

    cudaFuncSetAttribute(attn_kernel,
                         cudaFuncAttributeMaxDynamicSharedMemorySize,
                         ATTN_SMEM_BYTES);

    // prep: im2col hilo, weight hilo conversions
    gather_kernel<<<(BL_ * KCP_ + 255) / 256, 256>>>(x);
    packw_kernel<<<(D_ * KCP_ + 255) / 256, 256>>>(tok_w);
    packqkv_kernel<<<(NL_ * QS_ * D_ + 255) / 256, 256>>>(Wq, Wk, Wv, bq, bk, bv);
    f2hl_kernel<<<(NL_ * D_ * D_ + 255) / 256, 256>>>(Wo, wo_hi, wo_lo, NL_ * D_ * D_);
    f2hl_kernel<<<(NL_ * DFF_ * D_ + 255) / 256, 256>>>(W1, w1_hi, w1_lo, NL_ * DFF_ * D_);
    f2hl_kernel<<<(NL_ * D_ * DFF_ + 255) / 256, 256>>>(W2, w2_hi, w2_lo, NL_ * D_ * DFF_);
    f2hl_kernel<<<(C_ * D_ + 255) / 256, 256>>>(pw, pw_hi, pw_lo, C_ * D_);

    // token embedding: h = xg @ wp^T + pe  (fp32 + hilo out)
    launch_one<3>(xg_hi, xg_lo, wp_hi, wp_lo, nullptr, h, h_hi, h_lo,
                  BL_, D_, KCP_, pe);

    for (int l = 0; l < NL_; ++l) {
        // fused QKV projection (fp32 out only)
        launch_one<0>(h_hi, h_lo,
                      wqkv_hi + (size_t)l * QS_ * D_, wqkv_lo + (size_t)l * QS_ * D_,
                      bqkv + (size_t)l * QS_, qkv, nullptr, nullptr,
                      BL_, QS_, D_, nullptr);

        attn_kernel<<<B_ * H_, 256, ATTN_SMEM_BYTES>>>(qkv, o_hi, o_lo);

        // h += o @ Wo^T + bo  (fp32 rmw + hilo out)
        launch_one<1>(o_hi, o_lo,
                      wo_hi + (size_t)l * D_ * D_, wo_lo + (size_t)l * D_ * D_,
                      bo + (size_t)l * D_, h, h_hi, h_lo,
                      BL_, D_, D_, nullptr);
        // y = gelu(h @ W1^T + b1)  (hilo out only)
        launch_one<2>(h_hi, h_lo,
                      w1_hi + (size_t)l * DFF_ * D_, w1_lo + (size_t)l * DFF_ * D_,
                      b1 + (size_t)l * DFF_, nullptr, y_hi, y_lo,
                      BL_, DFF_, D_, nullptr);
        // h += y @ W2^T + b2  (fp32 rmw + hilo out)
        launch_one<1>(y_hi, y_lo,
                      w2_hi + (size_t)l * D_ * DFF_, w2_lo + (size_t)l * D_ * DFF_,
                      b2 + (size_t)l * D_, h, h_hi, h_lo,
                      BL_, D_, DFF_, nullptr);
    }

    // final projection -> output [B, L, C]  (fp32 only)
    launch_one<0>(h_hi, h_lo, pw_hi, pw_lo, pb, out, nullptr, nullptr,
                  BL_, C_, D_, nullptr);
}

// round 14
// speedup vs baseline: 1.5196x; 1.0305x over previous
#include <cuda_runtime.h>
#include <cuda_bf16.h>
#include <math.h>
#include <stdint.h>

// Problem constants
constexpr int B_   = 256;
constexpr int L_   = 100;
constexpr int C_   = 55;
constexpr int D_   = 512;
constexpr int H_   = 8;
constexpr int NL_  = 3;
constexpr int DFF_ = 64;
constexpr int DK_  = D_ / H_;      // 64
constexpr int BL_  = B_ * L_;      // 25600
constexpr int KC_  = 3 * C_;       // 165
constexpr int KCP_ = 192;          // padded K for conv GEMM
constexpr int QS_  = 3 * D_;       // fused qkv row stride (1536)

typedef __nv_bfloat16 bf16;

// ---------------- scratch (static device allocations) ----------------------
__device__ float g_h   [BL_ * D_];      // fp32 residual stream
__device__ float g_qkv [BL_ * QS_];     // fp32 (attention input)
__device__ float g_bqkv[NL_ * QS_];
// bf16 hi/lo planes (GEMM operands)
__device__ bf16 g_h_hi [BL_ * D_],   g_h_lo [BL_ * D_];
__device__ bf16 g_o_hi [BL_ * D_],   g_o_lo [BL_ * D_];
__device__ bf16 g_y_hi [BL_ * DFF_], g_y_lo [BL_ * DFF_];
__device__ bf16 g_xg_hi[BL_ * KCP_], g_xg_lo[BL_ * KCP_];
__device__ bf16 g_wp_hi[D_ * KCP_],  g_wp_lo[D_ * KCP_];
__device__ bf16 g_wqkv_hi[NL_ * QS_ * D_], g_wqkv_lo[NL_ * QS_ * D_];
__device__ bf16 g_wo_hi[NL_ * D_ * D_],    g_wo_lo[NL_ * D_ * D_];
__device__ bf16 g_w1_hi[NL_ * DFF_ * D_],  g_w1_lo[NL_ * DFF_ * D_];
__device__ bf16 g_w2_hi[NL_ * D_ * DFF_],  g_w2_lo[NL_ * D_ * DFF_];
__device__ bf16 g_pw_hi[C_ * D_],          g_pw_lo[C_ * D_];

// ---------------- split helpers ---------------------------------------------
__device__ __forceinline__ void splitE(float v, bf16& h, bf16& l) {
    h = __float2bfloat16(v);
    l = __float2bfloat16(v - __bfloat162float(h));
}

// ---------------- im2col gather -> hi/lo planes ------------------------------
__global__ void __launch_bounds__(256) gather_kernel(const float* __restrict__ x) {
    int idx = blockIdx.x * blockDim.x + threadIdx.x;
    const int total = BL_ * KCP_;
    if (idx >= total) return;
    int kk = idx % KCP_;
    int bl = idx / KCP_;
    float val = 0.f;
    if (kk < KC_) {
        int c = kk / 3, j = kk % 3;
        int b = bl / L_, l = bl % L_;
        int ls = l - 1 + j;
        if (ls < 0) ls += L_;
        if (ls >= L_) ls -= L_;
        val = x[((size_t)b * L_ + ls) * C_ + c];
    }
    splitE(val, g_xg_hi[idx], g_xg_lo[idx]);
}

__global__ void __launch_bounds__(256) packw_kernel(const float* __restrict__ w) {
    int idx = blockIdx.x * blockDim.x + threadIdx.x;
    const int total = D_ * KCP_;
    if (idx >= total) return;
    int kk = idx % KCP_;
    int r  = idx / KCP_;
    float v = (kk < KC_) ? w[(size_t)r * KC_ + kk] : 0.f;
    splitE(v, g_wp_hi[idx], g_wp_lo[idx]);
}

__global__ void __launch_bounds__(256) packqkv_kernel(
    const float* __restrict__ Wq, const float* __restrict__ Wk,
    const float* __restrict__ Wv,
    const float* __restrict__ bq, const float* __restrict__ bk,
    const float* __restrict__ bv)
{
    int idx = blockIdx.x * blockDim.x + threadIdx.x;
    const int perL = QS_ * D_;
    if (idx < NL_ * perL) {
        int l = idx / perL, rem = idx % perL;
        int row = rem / D_, col = rem % D_;
        const float* src = (row < D_) ? Wq : (row < 2 * D_) ? Wk : Wv;
        int r = row % D_;
        splitE(src[((size_t)l * D_ + r) * D_ + col], g_wqkv_hi[idx], g_wqkv_lo[idx]);
    }
    if (idx < NL_ * QS_) {
        int l = idx / QS_, row = idx % QS_;
        const float* src = (row < D_) ? bq : (row < 2 * D_) ? bk : bv;
        g_bqkv[idx] = src[(size_t)l * D_ + row % D_];
    }
}

__global__ void __launch_bounds__(256) f2hl_kernel(
    const float* __restrict__ in, bf16* __restrict__ hi, bf16* __restrict__ lo,
    int n)
{
    int i = blockIdx.x * blockDim.x + threadIdx.x;
    if (i >= n) return;
    splitE(in[i], hi[i], lo[i]);
}

// ---------------- mma / ldmatrix helpers ------------------------------------
#define MMA_BF16(C, A0, A1, A2, A3, B0, B1)                                   \
    asm volatile(                                                             \
        "mma.sync.aligned.m16n8k16.row.col.f32.bf16.bf16.f32 "                \
        "{%0,%1,%2,%3}, {%4,%5,%6,%7}, {%8,%9}, {%0,%1,%2,%3};\n"             \
        : "+f"(C[0]), "+f"(C[1]), "+f"(C[2]), "+f"(C[3])                      \
        : "r"(A0), "r"(A1), "r"(A2), "r"(A3), "r"(B0), "r"(B1))

__device__ __forceinline__ void ldsm4(uint32_t& r0, uint32_t& r1,
                                      uint32_t& r2, uint32_t& r3,
                                      uint32_t addr) {
    asm volatile(
        "ldmatrix.sync.aligned.m8n8.x4.shared.b16 {%0,%1,%2,%3}, [%4];\n"
        : "=r"(r0), "=r"(r1), "=r"(r2), "=r"(r3) : "r"(addr));
}

#define CP16(dst, src)                                                        \
    asm volatile("cp.async.ca.shared.global [%0], [%1], 16;\n"                \
                 :: "r"(dst), "l"(src))
#define CP16Z(dst, src, nbytes)                                               \
    asm volatile("cp.async.ca.shared.global [%0], [%1], 16, %2;\n"            \
                 :: "r"(dst), "l"(src), "r"(nbytes))

// ---------------- bf16-split tensor-core GEMM, cp.async multi-stage ---------
// C [M,N] (+)= A[M,K] @ W[N,K]^T + bias; operands are pre-split bf16 hi/lo
// planes; 3-term product (AhBh + AhBl + AlBh) ~ fp32 precision.
// MODE: 0 fp32 out; 1 C += v, fp32 + hilo out; 2 GELU, hilo out only;
//       3 +PE, fp32 + hilo out.
// Template tiles:
//   big:   BM=256, BN=128, WARPS_N=2 -> 64x64 warp tile (mma/ldsm ratio 6)
//   small: BM=128, BN=128, WARPS_N=4 -> 64x32 warp tile (round-13 proven)
template<int BM, int BN, int WARPS_N, int STAGES, int MODE>
__global__ void __launch_bounds__(256) mma_gemm(
    int M, int N, int K,
    const bf16* __restrict__ Agh, const bf16* __restrict__ Agl,
    const bf16* __restrict__ Bgh, const bf16* __restrict__ Bgl,
    const float* __restrict__ bias,
    float* __restrict__ Cp,
    bf16* __restrict__ Oh, bf16* __restrict__ Ol,
    const float* __restrict__ pe)
{
    constexpr int BK = 32;
    constexpr int WARPS_M = 8 / WARPS_N;
    constexpr int WM = BM / WARPS_M;
    constexpr int WN = BN / WARPS_N;
    constexpr int MT  = WM / 16;
    constexpr int NT2 = WN / 16;
    constexpr int ROWB    = 80;              // 64B data + 16B pad per row
    constexpr int PLANE_A = BM * ROWB;
    constexpr int PLANE_B = BN * ROWB;
    constexpr int STAGE_B = 2 * PLANE_A + 2 * PLANE_B;
    constexpr int AITER = BM * 4 / 256;      // cp.16 chunks per thread (A)
    constexpr int BITER = BN * 4 / 256;

    extern __shared__ uint32_t smw[];
    const uint32_t smemBase = (uint32_t)__cvta_generic_to_shared(smw);

    const int tid  = threadIdx.x;
    const int warp = tid >> 5, lane = tid & 31;
    const int wm = (warp / WARPS_N) * WM;
    const int wn = (warp % WARPS_N) * WN;
    const int g  = lane >> 2;
    const int tg = lane & 3;
    const int rowBase = blockIdx.y * BM;
    const int colBase = blockIdx.x * BN;

    // ldmatrix lane maps (proven rounds 7/11/13):
    const int aRow = lane & 15;
    const int aKB  = (lane >> 4) * 16;
    const uint32_t aOff = (uint32_t)((wm + aRow) * ROWB + aKB);
    const int bRow = (lane & 7) | (((lane >> 4) & 1) << 3);
    const int bKB  = ((lane >> 3) & 1) * 16;
    const uint32_t bOff = (uint32_t)((wn + bRow) * ROWB + bKB);

    float c[MT][2 * NT2][4];
    #pragma unroll
    for (int mt = 0; mt < MT; ++mt)
        #pragma unroll
        for (int nt = 0; nt < 2 * NT2; ++nt)
            #pragma unroll
            for (int j = 0; j < 4; ++j) c[mt][nt][j] = 0.f;

    auto loadStage = [&](int st, int k0) {
        const uint32_t sa = smemBase + (uint32_t)(st * STAGE_B);
        #pragma unroll
        for (int i = 0; i < AITER; ++i) {
            int f = tid + i * 256;
            int r = f >> 2, ch = f & 3;
            uint32_t d = sa + (uint32_t)(r * ROWB + ch * 16);
            size_t go = (size_t)(rowBase + r) * K + k0 + ch * 8;
            CP16(d, Agh + go);
            CP16(d + PLANE_A, Agl + go);
        }
        #pragma unroll
        for (int i = 0; i < BITER; ++i) {
            int f = tid + i * 256;
            int r = f >> 2, ch = f & 3;
            int gr = colBase + r;
            int nb = (gr < N) ? 16 : 0;
            int grc = (gr < N) ? gr : (N - 1);
            uint32_t d = sa + (uint32_t)(2 * PLANE_A + r * ROWB + ch * 16);
            size_t go = (size_t)grc * K + k0 + ch * 8;
            CP16Z(d, Bgh + go, nb);
            CP16Z(d + PLANE_B, Bgl + go, nb);
        }
    };

    auto compute = [&](int st) {
        const uint32_t stage = smemBase + (uint32_t)(st * STAGE_B);
        const uint32_t AhB = stage + aOff;
        const uint32_t AlB = AhB + PLANE_A;
        const uint32_t BhB = stage + 2 * PLANE_A + bOff;
        const uint32_t BlB = BhB + PLANE_B;
        #pragma unroll
        for (int ks = 0; ks < 2; ++ks) {
            const uint32_t kOfs = ks * 32;
            uint32_t ah[MT][4], al[MT][4], bh[NT2][4], bl[NT2][4];
            #pragma unroll
            for (int mt = 0; mt < MT; ++mt) {
                ldsm4(ah[mt][0], ah[mt][1], ah[mt][2], ah[mt][3],
                      AhB + mt * 16 * ROWB + kOfs);
                ldsm4(al[mt][0], al[mt][1], al[mt][2], al[mt][3],
                      AlB + mt * 16 * ROWB + kOfs);
            }
            #pragma unroll
            for (int n2 = 0; n2 < NT2; ++n2) {
                ldsm4(bh[n2][0], bh[n2][1], bh[n2][2], bh[n2][3],
                      BhB + n2 * 16 * ROWB + kOfs);
                ldsm4(bl[n2][0], bl[n2][1], bl[n2][2], bl[n2][3],
                      BlB + n2 * 16 * ROWB + kOfs);
            }
            #pragma unroll
            for (int mt = 0; mt < MT; ++mt)
                #pragma unroll
                for (int n2 = 0; n2 < NT2; ++n2)
                    #pragma unroll
                    for (int half = 0; half < 2; ++half) {
                        float* cc = c[mt][n2 * 2 + half];
                        uint32_t b0h = bh[n2][half * 2],
                                 b1h = bh[n2][half * 2 + 1];
                        uint32_t b0l = bl[n2][half * 2],
                                 b1l = bl[n2][half * 2 + 1];
                        MMA_BF16(cc, ah[mt][0], ah[mt][1], ah[mt][2],
                                 ah[mt][3], b0h, b1h);
                        MMA_BF16(cc, ah[mt][0], ah[mt][1], ah[mt][2],
                                 ah[mt][3], b0l, b1l);
                        MMA_BF16(cc, al[mt][0], al[mt][1], al[mt][2],
                                 al[mt][3], b0h, b1h);
                    }
        }
    };

    const int nIter = K / BK;
    for (int st = 0; st < STAGES - 1; ++st) {
        if (st < nIter) loadStage(st, st * BK);
        asm volatile("cp.async.commit_group;\n");
    }
    for (int it = 0; it < nIter; ++it) {
        asm volatile("cp.async.wait_group %0;\n" :: "n"(STAGES - 2));
        __syncthreads();
        compute(it % STAGES);
        int pi = it + STAGES - 1;
        if (pi < nIter) loadStage(pi % STAGES, pi * BK);
        asm volatile("cp.async.commit_group;\n");
    }

    // epilogue
    #pragma unroll
    for (int mt = 0; mt < MT; ++mt) {
        #pragma unroll
        for (int nt = 0; nt < 2 * NT2; ++nt) {
            int r0 = rowBase + wm + mt * 16 + g;
            int c0 = colBase + wn + nt * 8 + tg * 2;
            #pragma unroll
            for (int half = 0; half < 2; ++half) {
                int r = r0 + half * 8;
                if (c0 + 1 < N) {
                    float v0 = c[mt][nt][half * 2 + 0];
                    float v1 = c[mt][nt][half * 2 + 1];
                    if (bias) { v0 += bias[c0]; v1 += bias[c0 + 1]; }
                    if (MODE == 3) {
                        const float* per = pe + (size_t)(r % L_) * N;
                        v0 += per[c0]; v1 += per[c0 + 1];
                    }
                    if (MODE == 2) {
                        v0 = 0.5f * v0 * (1.f + erff(v0 * 0.70710678118654752f));
                        v1 = 0.5f * v1 * (1.f + erff(v1 * 0.70710678118654752f));
                    }
                    size_t off = (size_t)r * N + c0;
                    if (MODE == 1) {
                        v0 += Cp[off]; v1 += Cp[off + 1];
                    }
                    if (MODE != 2) {
                        Cp[off] = v0; Cp[off + 1] = v1;
                    }
                    if (MODE == 1 || MODE == 2 || MODE == 3) {
                        bf16 h0, l0, h1, l1;
                        splitE(v0, h0, l0);
                        splitE(v1, h1, l1);
                        Oh[off] = h0; Oh[off + 1] = h1;
                        Ol[off] = l0; Ol[off + 1] = l1;
                    }
                } else if (c0 < N) {   // single-column tail (N=55 proj)
                    float v0 = c[mt][nt][half * 2 + 0];
                    if (bias) v0 += bias[c0];
                    size_t off = (size_t)r * N + c0;
                    if (MODE != 2) Cp[off] = v0;
                }
            }
        }
    }
}

// ---------------- attention: one CTA per (b, h), writes o hilo ---------------
constexpr int S_STRIDE = 104;
constexpr int ATTN_SMEM_FLOATS = L_ * S_STRIDE + L_ * DK_ + DK_ * L_;
constexpr int ATTN_SMEM_BYTES  = ATTN_SMEM_FLOATS * 4;   // 92800 B

__global__ void __launch_bounds__(256) attn_kernel(
    const float* __restrict__ qkv,   // [BL][1536]: q|k|v
    bf16* __restrict__ ohp, bf16* __restrict__ olp)
{
    extern __shared__ float sm[];
    float* S   = sm;                          // [100][104]
    float* qs  = sm + L_ * S_STRIDE;          // [100][64]
    float* kst = qs + L_ * DK_;               // [64][100] (reused for v)

    const int b = blockIdx.x / H_;
    const int h = blockIdx.x % H_;
    const float* qb = qkv + ((size_t)b * L_) * QS_ + h * DK_;
    const float* kb = qb + D_;
    const float* vb = qb + 2 * D_;
    bf16* obh = ohp + ((size_t)b * L_) * D_ + h * DK_;
    bf16* obl = olp + ((size_t)b * L_) * D_ + h * DK_;
    const int tid = threadIdx.x;

    for (int idx = tid; idx < L_ * DK_; idx += blockDim.x) {
        int r = idx / DK_, e = idx % DK_;
        qs [r * DK_ + e] = qb[(size_t)r * QS_ + e];
        kst[e * L_  + r] = kb[(size_t)r * QS_ + e];
    }
    __syncthreads();

    const float scale = 0.125f;
    for (int p = tid; p < L_ * (L_ / 4); p += blockDim.x) {
        int i  = p / (L_ / 4);
        int j4 = (p % (L_ / 4)) * 4;
        float s0 = 0.f, s1 = 0.f, s2 = 0.f, s3 = 0.f;
        #pragma unroll 8
        for (int e = 0; e < DK_; ++e) {
            float qv = qs[i * DK_ + e];
            const float4 kv = *reinterpret_cast<const float4*>(kst + e * L_ + j4);
            s0 = fmaf(qv, kv.x, s0);
            s1 = fmaf(qv, kv.y, s1);
            s2 = fmaf(qv, kv.z, s2);
            s3 = fmaf(qv, kv.w, s3);
        }
        *reinterpret_cast<float4*>(S + i * S_STRIDE + j4) =
            make_float4(s0 * scale, s1 * scale, s2 * scale, s3 * scale);
    }
    __syncthreads();

    float* vs = kst;
    for (int idx = tid; idx < L_ * DK_; idx += blockDim.x) {
        int r = idx / DK_, e = idx % DK_;
        vs[r * DK_ + e] = vb[(size_t)r * QS_ + e];
    }
    {
        int warp = tid >> 5, lane = tid & 31;
        for (int i = warp; i < L_; i += (int)(blockDim.x >> 5)) {
            float* Sr = S + i * S_STRIDE;
            float m = -1e30f;
            for (int j = lane; j < L_; j += 32) m = fmaxf(m, Sr[j]);
            #pragma unroll
            for (int off = 16; off; off >>= 1)
                m = fmaxf(m, __shfl_xor_sync(0xffffffff, m, off));
            float sum = 0.f;
            for (int j = lane; j < L_; j += 32) {
                float ev = __expf(Sr[j] - m);
                Sr[j] = ev;
                sum += ev;
            }
            #pragma unroll
            for (int off = 16; off; off >>= 1)
                sum += __shfl_xor_sync(0xffffffff, sum, off);
            float inv = 1.f / sum;
            for (int j = lane; j < L_; j += 32) Sr[j] *= inv;
        }
    }
    __syncthreads();

    for (int idx = tid; idx < L_ * DK_; idx += blockDim.x) {
        int i = idx / DK_, d = idx % DK_;
        const float* Sr = S + i * S_STRIDE;
        float a0 = 0.f, a1 = 0.f, a2 = 0.f, a3 = 0.f;
        #pragma unroll 4
        for (int j = 0; j < L_; j += 4) {
            a0 = fmaf(Sr[j    ], vs[(j    ) * DK_ + d], a0);
            a1 = fmaf(Sr[j + 1], vs[(j + 1) * DK_ + d], a1);
            a2 = fmaf(Sr[j + 2], vs[(j + 2) * DK_ + d], a2);
            a3 = fmaf(Sr[j + 3], vs[(j + 3) * DK_ + d], a3);
        }
        float v = (a0 + a1) + (a2 + a3);
        bf16 hh, ll;
        splitE(v, hh, ll);
        obh[(size_t)i * D_ + d] = hh;
        obl[(size_t)i * D_ + d] = ll;
    }
}

// ---------------- host-side launch helpers -----------------------------------
// big: BM=256, BN=128, 3 stages -> (2*256+2*128)*80*3 = 184320 B smem
// small: BM=128, BN=128, 4 stages -> 163840 B smem
template<int MODE>
static void launch_big(const bf16* Ah, const bf16* Al,
                       const bf16* Bh, const bf16* Bl,
                       const float* bias, float* C,
                       bf16* Oh, bf16* Ol,
                       int M, int N, int K, const float* pe) {
    constexpr int SMEM = (2 * 256 + 2 * 128) * 80 * 3;
    static bool done = false;
    if (!done) {
        cudaFuncSetAttribute(mma_gemm<256, 128, 2, 3, MODE>,
                             cudaFuncAttributeMaxDynamicSharedMemorySize, SMEM);
        done = true;
    }
    dim3 grid(N / 128, M / 256);
    mma_gemm<256, 128, 2, 3, MODE><<<grid, 256, SMEM>>>(
        M, N, K, Ah, Al, Bh, Bl, bias, C, Oh, Ol, pe);
}

template<int MODE>
static void launch_small(const bf16* Ah, const bf16* Al,
                         const bf16* Bh, const bf16* Bl,
                         const float* bias, float* C,
                         bf16* Oh, bf16* Ol,
                         int M, int N, int K, const float* pe) {
    constexpr int SMEM = (2 * 128 + 2 * 128) * 80 * 4;
    static bool done = false;
    if (!done) {
        cudaFuncSetAttribute(mma_gemm<128, 128, 4, 4, MODE>,
                             cudaFuncAttributeMaxDynamicSharedMemorySize, SMEM);
        done = true;
    }
    dim3 grid((N + 127) / 128, M / 128);
    mma_gemm<128, 128, 4, 4, MODE><<<grid, 256, SMEM>>>(
        M, N, K, Ah, Al, Bh, Bl, bias, C, Oh, Ol, pe);
}

extern "C" void kernel_launch(void* const* d_in, const int* in_sizes, int n_in,
                              void* d_out, int out_size) {
    (void)in_sizes; (void)n_in; (void)out_size;
    const float* x     = (const float*)d_in[0];
    const float* tok_w = (const float*)d_in[1];
    const float* pe    = (const float*)d_in[2];
    const float* Wq    = (const float*)d_in[3];
    const float* bq    = (const float*)d_in[4];
    const float* Wk    = (const float*)d_in[5];
    const float* bk    = (const float*)d_in[6];
    const float* Wv    = (const float*)d_in[7];
    const float* bv    = (const float*)d_in[8];
    // d_in[9]/d_in[10] (Wsig/bsig): prior branch never reaches output -> skipped
    const float* Wo    = (const float*)d_in[11];
    const float* bo    = (const float*)d_in[12];
    const float* W1    = (const float*)d_in[13];
    const float* b1    = (const float*)d_in[14];
    const float* W2    = (const float*)d_in[15];
    const float* b2    = (const float*)d_in[16];
    const float* pw    = (const float*)d_in[17];
    const float* pb    = (const float*)d_in[18];
    float* out = (float*)d_out;

    float *h, *qkv, *bqkv;
    bf16 *h_hi, *h_lo, *o_hi, *o_lo, *y_hi, *y_lo, *xg_hi, *xg_lo;
    bf16 *wp_hi, *wp_lo, *wqkv_hi, *wqkv_lo, *wo_hi, *wo_lo;
    bf16 *w1_hi, *w1_lo, *w2_hi, *w2_lo, *pw_hi, *pw_lo;
    cudaGetSymbolAddress((void**)&h,    g_h);
    cudaGetSymbolAddress((void**)&qkv,  g_qkv);
    cudaGetSymbolAddress((void**)&bqkv, g_bqkv);
    cudaGetSymbolAddress((void**)&h_hi, g_h_hi);   cudaGetSymbolAddress((void**)&h_lo, g_h_lo);
    cudaGetSymbolAddress((void**)&o_hi, g_o_hi);   cudaGetSymbolAddress((void**)&o_lo, g_o_lo);
    cudaGetSymbolAddress((void**)&y_hi, g_y_hi);   cudaGetSymbolAddress((void**)&y_lo, g_y_lo);
    cudaGetSymbolAddress((void**)&xg_hi, g_xg_hi); cudaGetSymbolAddress((void**)&xg_lo, g_xg_lo);
    cudaGetSymbolAddress((void**)&wp_hi, g_wp_hi); cudaGetSymbolAddress((void**)&wp_lo, g_wp_lo);
    cudaGetSymbolAddress((void**)&wqkv_hi, g_wqkv_hi); cudaGetSymbolAddress((void**)&wqkv_lo, g_wqkv_lo);
    cudaGetSymbolAddress((void**)&wo_hi, g_wo_hi); cudaGetSymbolAddress((void**)&wo_lo, g_wo_lo);
    cudaGetSymbolAddress((void**)&w1_hi, g_w1_hi); cudaGetSymbolAddress((void**)&w1_lo, g_w1_lo);
    cudaGetSymbolAddress((void**)&w2_hi, g_w2_hi); cudaGetSymbolAddress((void**)&w2_lo, g_w2_lo);
    cudaGetSymbolAddress((void**)&pw_hi, g_pw_hi); cudaGetSymbolAddress((void**)&pw_lo, g_pw_lo);

    cudaFuncSetAttribute(attn_kernel,
                         cudaFuncAttributeMaxDynamicSharedMemorySize,
                         ATTN_SMEM_BYTES);

    // prep: im2col hilo, weight hilo conversions
    gather_kernel<<<(BL_ * KCP_ + 255) / 256, 256>>>(x);
    packw_kernel<<<(D_ * KCP_ + 255) / 256, 256>>>(tok_w);
    packqkv_kernel<<<(NL_ * QS_ * D_ + 255) / 256, 256>>>(Wq, Wk, Wv, bq, bk, bv);
    f2hl_kernel<<<(NL_ * D_ * D_ + 255) / 256, 256>>>(Wo, wo_hi, wo_lo, NL_ * D_ * D_);
    f2hl_kernel<<<(NL_ * DFF_ * D_ + 255) / 256, 256>>>(W1, w1_hi, w1_lo, NL_ * DFF_ * D_);
    f2hl_kernel<<<(NL_ * D_ * DFF_ + 255) / 256, 256>>>(W2, w2_hi, w2_lo, NL_ * D_ * DFF_);
    f2hl_kernel<<<(C_ * D_ + 255) / 256, 256>>>(pw, pw_hi, pw_lo, C_ * D_);

    // token embedding: h = xg @ wp^T + pe  (fp32 + hilo out)
    launch_big<3>(xg_hi, xg_lo, wp_hi, wp_lo, nullptr, h, h_hi, h_lo,
                  BL_, D_, KCP_, pe);

    for (int l = 0; l < NL_; ++l) {
        // fused QKV projection (fp32 out only)
        launch_big<0>(h_hi, h_lo,
                      wqkv_hi + (size_t)l * QS_ * D_, wqkv_lo + (size_t)l * QS_ * D_,
                      bqkv + (size_t)l * QS_, qkv, nullptr, nullptr,
                      BL_, QS_, D_, nullptr);

        attn_kernel<<<B_ * H_, 256, ATTN_SMEM_BYTES>>>(qkv, o_hi, o_lo);

        // h += o @ Wo^T + bo  (fp32 rmw + hilo out)
        launch_big<1>(o_hi, o_lo,
                      wo_hi + (size_t)l * D_ * D_, wo_lo + (size_t)l * D_ * D_,
                      bo + (size_t)l * D_, h, h_hi, h_lo,
                      BL_, D_, D_, nullptr);
        // y = gelu(h @ W1^T + b1)  (hilo out only)
        launch_small<2>(h_hi, h_lo,
                        w1_hi + (size_t)l * DFF_ * D_, w1_lo + (size_t)l * DFF_ * D_,
                        b1 + (size_t)l * DFF_, nullptr, y_hi, y_lo,
                        BL_, DFF_, D_, nullptr);
        // h += y @ W2^T + b2  (fp32 rmw + hilo out)
        launch_big<1>(y_hi, y_lo,
                      w2_hi + (size_t)l * D_ * DFF_, w2_lo + (size_t)l * D_ * DFF_,
                      b2 + (size_t)l * D_, h, h_hi, h_lo,
                      BL_, D_, DFF_, nullptr);
    }

    // final projection -> output [B, L, C]  (fp32 only)
    launch_small<0>(h_hi, h_lo, pw_hi, pw_lo, pb, out, nullptr, nullptr,
                    BL_, C_, D_, nullptr);
}

// round 17
// speedup vs baseline: 1.5760x; 1.0371x over previous
#include <cuda_runtime.h>
#include <cuda_bf16.h>
#include <math.h>
#include <stdint.h>

// Problem constants
constexpr int B_   = 256;
constexpr int L_   = 100;
constexpr int C_   = 55;
constexpr int D_   = 512;
constexpr int H_   = 8;
constexpr int NL_  = 3;
constexpr int DFF_ = 64;
constexpr int DK_  = D_ / H_;      // 64
constexpr int BL_  = B_ * L_;      // 25600
constexpr int KC_  = 3 * C_;       // 165
constexpr int KCP_ = 192;          // padded K for conv GEMM
constexpr int QS_  = 3 * D_;       // fused qkv row stride (1536)

typedef __nv_bfloat16 bf16;

// ---------------- scratch (static device allocations) ----------------------
__device__ float g_h   [BL_ * D_];      // fp32 residual stream
__device__ float g_qkv [BL_ * QS_];     // fp32 (attention input)
__device__ float g_bqkv[NL_ * QS_];
// bf16 hi/lo planes (GEMM operands)
__device__ bf16 g_h_hi [BL_ * D_],   g_h_lo [BL_ * D_];
__device__ bf16 g_o_hi [BL_ * D_],   g_o_lo [BL_ * D_];
__device__ bf16 g_y_hi [BL_ * DFF_], g_y_lo [BL_ * DFF_];
__device__ bf16 g_xg_hi[BL_ * KCP_], g_xg_lo[BL_ * KCP_];
__device__ bf16 g_wp_hi[D_ * KCP_],  g_wp_lo[D_ * KCP_];
__device__ bf16 g_wqkv_hi[NL_ * QS_ * D_], g_wqkv_lo[NL_ * QS_ * D_];
__device__ bf16 g_wo_hi[NL_ * D_ * D_],    g_wo_lo[NL_ * D_ * D_];
__device__ bf16 g_w1_hi[NL_ * DFF_ * D_],  g_w1_lo[NL_ * DFF_ * D_];
__device__ bf16 g_w2_hi[NL_ * D_ * DFF_],  g_w2_lo[NL_ * D_ * DFF_];
__device__ bf16 g_pw_hi[C_ * D_],          g_pw_lo[C_ * D_];

// ---------------- split helpers ---------------------------------------------
__device__ __forceinline__ void splitE(float v, bf16& h, bf16& l) {
    h = __float2bfloat16(v);
    l = __float2bfloat16(v - __bfloat162float(h));
}

// ---------------- prep kernels ----------------------------------------------
__global__ void __launch_bounds__(256) gather_kernel(const float* __restrict__ x) {
    int idx = blockIdx.x * blockDim.x + threadIdx.x;
    const int total = BL_ * KCP_;
    if (idx >= total) return;
    int kk = idx % KCP_;
    int bl = idx / KCP_;
    float val = 0.f;
    if (kk < KC_) {
        int c = kk / 3, j = kk % 3;
        int b = bl / L_, l = bl % L_;
        int ls = l - 1 + j;
        if (ls < 0) ls += L_;
        if (ls >= L_) ls -= L_;
        val = x[((size_t)b * L_ + ls) * C_ + c];
    }
    splitE(val, g_xg_hi[idx], g_xg_lo[idx]);
}

__global__ void __launch_bounds__(256) packw_kernel(const float* __restrict__ w) {
    int idx = blockIdx.x * blockDim.x + threadIdx.x;
    const int total = D_ * KCP_;
    if (idx >= total) return;
    int kk = idx % KCP_;
    int r  = idx / KCP_;
    float v = (kk < KC_) ? w[(size_t)r * KC_ + kk] : 0.f;
    splitE(v, g_wp_hi[idx], g_wp_lo[idx]);
}

__global__ void __launch_bounds__(256) packqkv_kernel(
    const float* __restrict__ Wq, const float* __restrict__ Wk,
    const float* __restrict__ Wv,
    const float* __restrict__ bq, const float* __restrict__ bk,
    const float* __restrict__ bv)
{
    int idx = blockIdx.x * blockDim.x + threadIdx.x;
    const int perL = QS_ * D_;
    if (idx < NL_ * perL) {
        int l = idx / perL, rem = idx % perL;
        int row = rem / D_, col = rem % D_;
        const float* src = (row < D_) ? Wq : (row < 2 * D_) ? Wk : Wv;
        int r = row % D_;
        splitE(src[((size_t)l * D_ + r) * D_ + col], g_wqkv_hi[idx], g_wqkv_lo[idx]);
    }
    if (idx < NL_ * QS_) {
        int l = idx / QS_, row = idx % QS_;
        const float* src = (row < D_) ? bq : (row < 2 * D_) ? bk : bv;
        g_bqkv[idx] = src[(size_t)l * D_ + row % D_];
    }
}

__global__ void __launch_bounds__(256) f2hl_kernel(
    const float* __restrict__ in, bf16* __restrict__ hi, bf16* __restrict__ lo,
    int n)
{
    int i = blockIdx.x * blockDim.x + threadIdx.x;
    if (i >= n) return;
    splitE(in[i], hi[i], lo[i]);
}

// ---------------- mma / ldmatrix / cp.async helpers --------------------------
#define MMA_BF16(C, A0, A1, A2, A3, B0, B1)                                   \
    asm volatile(                                                             \
        "mma.sync.aligned.m16n8k16.row.col.f32.bf16.bf16.f32 "                \
        "{%0,%1,%2,%3}, {%4,%5,%6,%7}, {%8,%9}, {%0,%1,%2,%3};\n"             \
        : "+f"(C[0]), "+f"(C[1]), "+f"(C[2]), "+f"(C[3])                      \
        : "r"(A0), "r"(A1), "r"(A2), "r"(A3), "r"(B0), "r"(B1))

__device__ __forceinline__ void ldsm4(uint32_t& r0, uint32_t& r1,
                                      uint32_t& r2, uint32_t& r3,
                                      uint32_t addr) {
    asm volatile(
        "ldmatrix.sync.aligned.m8n8.x4.shared.b16 {%0,%1,%2,%3}, [%4];\n"
        : "=r"(r0), "=r"(r1), "=r"(r2), "=r"(r3) : "r"(addr));
}

#define CP16(dst, src)                                                        \
    asm volatile("cp.async.ca.shared.global [%0], [%1], 16;\n"                \
                 :: "r"(dst), "l"(src))
#define CP16Z(dst, src, nbytes)                                               \
    asm volatile("cp.async.ca.shared.global [%0], [%1], 16, %2;\n"            \
                 :: "r"(dst), "l"(src), "r"(nbytes))

// SW64 swizzle for 64-byte rows (conflict-free for 16B cp.async stores and
// ldmatrix phases: mod-128 slot = (r&1)*64 + (c^((r>>1)&3))*16, all distinct
// over 8 consecutive rows).
__device__ __forceinline__ uint32_t sw64(uint32_t off) {
    return off ^ ((off >> 3) & 0x30);
}

// ---------------- bf16-split tensor-core GEMM, 2 CTAs/SM ---------------------
// C [M,N] (+)= A[M,K] @ W[N,K]^T + bias; operands pre-split bf16 hi/lo planes;
// 3-term product (AhBh + AhBl + AlBh) ~ fp32 precision.
// BM=BN=128, 64x32 warp tile, BK=32, 64B swizzled rows -> 32KB/stage,
// 3 stages = 96KB smem  =>  TWO CTAs co-resident per SM (the round-15 theory:
// HMMA pipe idle 70% with 1 CTA/SM; co-resident CTA fills wait/sync bubbles).
// MODE: 0 fp32 out; 1 C+=v, fp32+hilo out; 2 GELU, hilo only; 3 +PE, fp32+hilo.
constexpr int GBM = 128, GBN = 128, GBK = 32;
constexpr int ROWB2   = 64;                  // bytes per row (32 bf16, no pad)
constexpr int PLANE2  = GBM * ROWB2;         // 8192 B
constexpr int STAGE2  = 4 * PLANE2;          // Ah|Al|Bh|Bl = 32768 B
constexpr int NST2    = 3;
constexpr int G_SMEM  = NST2 * STAGE2;       // 98304 B

template<int MODE>
__global__ void __launch_bounds__(256, 2) mma_gemm(
    int M, int N, int K,
    const bf16* __restrict__ Agh, const bf16* __restrict__ Agl,
    const bf16* __restrict__ Bgh, const bf16* __restrict__ Bgl,
    const float* __restrict__ bias,
    float* __restrict__ Cp,
    bf16* __restrict__ Oh, bf16* __restrict__ Ol,
    const float* __restrict__ pe)
{
    constexpr int WM = 64, WN = 32;          // 2x4 warp grid
    constexpr int MT  = WM / 16;             // 4
    constexpr int NT2 = WN / 16;             // 2

    extern __shared__ uint32_t smw[];
    const uint32_t smemBase = (uint32_t)__cvta_generic_to_shared(smw);

    const int tid  = threadIdx.x;
    const int warp = tid >> 5, lane = tid & 31;
    const int wm = (warp >> 2) * WM;
    const int wn = (warp & 3) * WN;
    const int g  = lane >> 2;
    const int tg = lane & 3;
    const int rowBase = blockIdx.y * GBM;
    const int colBase = blockIdx.x * GBN;

    // ldmatrix lane maps (proven rounds 7/11/13/14); byte offsets now on
    // 64B row stride, swizzled at use.
    const int aRow = lane & 15;
    const int aKB  = (lane >> 4) * 16;
    const uint32_t aOff = (uint32_t)((wm + aRow) * ROWB2 + aKB);
    const int bRow = (lane & 7) | (((lane >> 4) & 1) << 3);
    const int bKB  = ((lane >> 3) & 1) * 16;
    const uint32_t bOff = (uint32_t)((wn + bRow) * ROWB2 + bKB);

    float c[MT][2 * NT2][4];
    #pragma unroll
    for (int mt = 0; mt < MT; ++mt)
        #pragma unroll
        for (int nt = 0; nt < 2 * NT2; ++nt)
            #pragma unroll
            for (int j = 0; j < 4; ++j) c[mt][nt][j] = 0.f;

    auto loadStage = [&](int st, int k0) {
        const uint32_t sa = smemBase + (uint32_t)(st * STAGE2);
        // 128 rows x 4 chunks of 16B per plane = 512 chunks; 2 per thread
        #pragma unroll
        for (int i = 0; i < 2; ++i) {
            int id = tid + (i << 8);
            int r = id >> 2, ch = id & 3;
            uint32_t sw = sw64((uint32_t)(r * ROWB2 + ch * 16));
            size_t goA = (size_t)(rowBase + r) * K + k0 + ch * 8;
            CP16(sa + sw, Agh + goA);
            CP16(sa + PLANE2 + sw, Agl + goA);
            int gr = colBase + r;
            uint32_t nb = (gr < N) ? 16u : 0u;
            size_t goB = (size_t)((gr < N) ? gr : 0) * K + k0 + ch * 8;
            CP16Z(sa + 2 * PLANE2 + sw, Bgh + goB, nb);
            CP16Z(sa + 3 * PLANE2 + sw, Bgl + goB, nb);
        }
    };

    auto compute = [&](int st) {
        const uint32_t stage = smemBase + (uint32_t)(st * STAGE2);
        #pragma unroll
        for (int ks = 0; ks < 2; ++ks) {
            const uint32_t kOfs = ks * 32;
            uint32_t ah[MT][4], al[MT][4];
            #pragma unroll
            for (int mt = 0; mt < MT; ++mt) {
                uint32_t off = aOff + (uint32_t)(mt * 16 * ROWB2) + kOfs;
                uint32_t sw  = sw64(off);
                ldsm4(ah[mt][0], ah[mt][1], ah[mt][2], ah[mt][3], stage + sw);
                ldsm4(al[mt][0], al[mt][1], al[mt][2], al[mt][3],
                      stage + PLANE2 + sw);
            }
            #pragma unroll
            for (int n2 = 0; n2 < NT2; ++n2) {
                uint32_t off = bOff + (uint32_t)(n2 * 16 * ROWB2) + kOfs;
                uint32_t sw  = sw64(off);
                uint32_t bh[4], bl[4];
                ldsm4(bh[0], bh[1], bh[2], bh[3], stage + 2 * PLANE2 + sw);
                ldsm4(bl[0], bl[1], bl[2], bl[3], stage + 3 * PLANE2 + sw);
                #pragma unroll
                for (int mt = 0; mt < MT; ++mt)
                    #pragma unroll
                    for (int half = 0; half < 2; ++half) {
                        float* cc = c[mt][n2 * 2 + half];
                        MMA_BF16(cc, ah[mt][0], ah[mt][1], ah[mt][2],
                                 ah[mt][3], bh[half * 2], bh[half * 2 + 1]);
                        MMA_BF16(cc, ah[mt][0], ah[mt][1], ah[mt][2],
                                 ah[mt][3], bl[half * 2], bl[half * 2 + 1]);
                        MMA_BF16(cc, al[mt][0], al[mt][1], al[mt][2],
                                 al[mt][3], bh[half * 2], bh[half * 2 + 1]);
                    }
            }
        }
    };

    const int nIter = K / GBK;
    for (int st = 0; st < NST2 - 1; ++st) {
        if (st < nIter) loadStage(st, st * GBK);
        asm volatile("cp.async.commit_group;\n");
    }
    for (int it = 0; it < nIter; ++it) {
        asm volatile("cp.async.wait_group %0;\n" :: "n"(NST2 - 2));
        __syncthreads();
        compute(it % NST2);
        int pi = it + NST2 - 1;
        if (pi < nIter) loadStage(pi % NST2, pi * GBK);
        asm volatile("cp.async.commit_group;\n");
    }

    // epilogue
    #pragma unroll
    for (int mt = 0; mt < MT; ++mt) {
        #pragma unroll
        for (int nt = 0; nt < 2 * NT2; ++nt) {
            int r0 = rowBase + wm + mt * 16 + g;
            int c0 = colBase + wn + nt * 8 + tg * 2;
            #pragma unroll
            for (int half = 0; half < 2; ++half) {
                int r = r0 + half * 8;
                if (c0 + 1 < N) {
                    float v0 = c[mt][nt][half * 2 + 0];
                    float v1 = c[mt][nt][half * 2 + 1];
                    if (bias) { v0 += bias[c0]; v1 += bias[c0 + 1]; }
                    if (MODE == 3) {
                        const float* per = pe + (size_t)(r % L_) * N;
                        v0 += per[c0]; v1 += per[c0 + 1];
                    }
                    if (MODE == 2) {
                        v0 = 0.5f * v0 * (1.f + erff(v0 * 0.70710678118654752f));
                        v1 = 0.5f * v1 * (1.f + erff(v1 * 0.70710678118654752f));
                    }
                    size_t off = (size_t)r * N + c0;
                    if (MODE == 1) {
                        v0 += Cp[off]; v1 += Cp[off + 1];
                    }
                    if (MODE != 2) {
                        Cp[off] = v0; Cp[off + 1] = v1;
                    }
                    if (MODE == 1 || MODE == 2 || MODE == 3) {
                        bf16 h0, l0, h1, l1;
                        splitE(v0, h0, l0);
                        splitE(v1, h1, l1);
                        Oh[off] = h0; Oh[off + 1] = h1;
                        Ol[off] = l0; Ol[off + 1] = l1;
                    }
                } else if (c0 < N) {   // single-column tail (N=55 proj)
                    float v0 = c[mt][nt][half * 2 + 0];
                    if (bias) v0 += bias[c0];
                    size_t off = (size_t)r * N + c0;
                    if (MODE != 2) Cp[off] = v0;
                }
            }
        }
    }
}

// ---------------- attention: one CTA per (b, h), writes o hilo ---------------
constexpr int S_STRIDE = 104;
constexpr int ATTN_SMEM_FLOATS = L_ * S_STRIDE + L_ * DK_ + DK_ * L_;
constexpr int ATTN_SMEM_BYTES  = ATTN_SMEM_FLOATS * 4;   // 92800 B

__global__ void __launch_bounds__(256) attn_kernel(
    const float* __restrict__ qkv,   // [BL][1536]: q|k|v
    bf16* __restrict__ ohp, bf16* __restrict__ olp)
{
    extern __shared__ float sm[];
    float* S   = sm;                          // [100][104]
    float* qs  = sm + L_ * S_STRIDE;          // [100][64]
    float* kst = qs + L_ * DK_;               // [64][100] (reused for v)

    const int b = blockIdx.x / H_;
    const int h = blockIdx.x % H_;
    const float* qb = qkv + ((size_t)b * L_) * QS_ + h * DK_;
    const float* kb = qb + D_;
    const float* vb = qb + 2 * D_;
    bf16* obh = ohp + ((size_t)b * L_) * D_ + h * DK_;
    bf16* obl = olp + ((size_t)b * L_) * D_ + h * DK_;
    const int tid = threadIdx.x;

    for (int idx = tid; idx < L_ * DK_; idx += blockDim.x) {
        int r = idx / DK_, e = idx % DK_;
        qs [r * DK_ + e] = qb[(size_t)r * QS_ + e];
        kst[e * L_  + r] = kb[(size_t)r * QS_ + e];
    }
    __syncthreads();

    const float scale = 0.125f;
    for (int p = tid; p < L_ * (L_ / 4); p += blockDim.x) {
        int i  = p / (L_ / 4);
        int j4 = (p % (L_ / 4)) * 4;
        float s0 = 0.f, s1 = 0.f, s2 = 0.f, s3 = 0.f;
        #pragma unroll 8
        for (int e = 0; e < DK_; ++e) {
            float qv = qs[i * DK_ + e];
            const float4 kv = *reinterpret_cast<const float4*>(kst + e * L_ + j4);
            s0 = fmaf(qv, kv.x, s0);
            s1 = fmaf(qv, kv.y, s1);
            s2 = fmaf(qv, kv.z, s2);
            s3 = fmaf(qv, kv.w, s3);
        }
        *reinterpret_cast<float4*>(S + i * S_STRIDE + j4) =
            make_float4(s0 * scale, s1 * scale, s2 * scale, s3 * scale);
    }
    __syncthreads();

    float* vs = kst;
    for (int idx = tid; idx < L_ * DK_; idx += blockDim.x) {
        int r = idx / DK_, e = idx % DK_;
        vs[r * DK_ + e] = vb[(size_t)r * QS_ + e];
    }
    {
        int warp = tid >> 5, lane = tid & 31;
        for (int i = warp; i < L_; i += (int)(blockDim.x >> 5)) {
            float* Sr = S + i * S_STRIDE;
            float m = -1e30f;
            for (int j = lane; j < L_; j += 32) m = fmaxf(m, Sr[j]);
            #pragma unroll
            for (int off = 16; off; off >>= 1)
                m = fmaxf(m, __shfl_xor_sync(0xffffffff, m, off));
            float sum = 0.f;
            for (int j = lane; j < L_; j += 32) {
                float ev = __expf(Sr[j] - m);
                Sr[j] = ev;
                sum += ev;
            }
            #pragma unroll
            for (int off = 16; off; off >>= 1)
                sum += __shfl_xor_sync(0xffffffff, sum, off);
            float inv = 1.f / sum;
            for (int j = lane; j < L_; j += 32) Sr[j] *= inv;
        }
    }
    __syncthreads();

    for (int idx = tid; idx < L_ * DK_; idx += blockDim.x) {
        int i = idx / DK_, d = idx % DK_;
        const float* Sr = S + i * S_STRIDE;
        float a0 = 0.f, a1 = 0.f, a2 = 0.f, a3 = 0.f;
        #pragma unroll 4
        for (int j = 0; j < L_; j += 4) {
            a0 = fmaf(Sr[j    ], vs[(j    ) * DK_ + d], a0);
            a1 = fmaf(Sr[j + 1], vs[(j + 1) * DK_ + d], a1);
            a2 = fmaf(Sr[j + 2], vs[(j + 2) * DK_ + d], a2);
            a3 = fmaf(Sr[j + 3], vs[(j + 3) * DK_ + d], a3);
        }
        float v = (a0 + a1) + (a2 + a3);
        bf16 hh, ll;
        splitE(v, hh, ll);
        obh[(size_t)i * D_ + d] = hh;
        obl[(size_t)i * D_ + d] = ll;
    }
}

// ---------------- host-side launch helper -----------------------------------
template<int MODE>
static void launch_one(const bf16* Ah, const bf16* Al,
                       const bf16* Bh, const bf16* Bl,
                       const float* bias, float* C,
                       bf16* Oh, bf16* Ol,
                       int M, int N, int K, const float* pe) {
    static bool done = false;
    if (!done) {
        cudaFuncSetAttribute(mma_gemm<MODE>,
                             cudaFuncAttributeMaxDynamicSharedMemorySize,
                             G_SMEM);
        done = true;
    }
    dim3 grid((N + 127) / 128, M / 128);
    mma_gemm<MODE><<<grid, 256, G_SMEM>>>(M, N, K, Ah, Al, Bh, Bl,
                                          bias, C, Oh, Ol, pe);
}

extern "C" void kernel_launch(void* const* d_in, const int* in_sizes, int n_in,
                              void* d_out, int out_size) {
    (void)in_sizes; (void)n_in; (void)out_size;
    const float* x     = (const float*)d_in[0];
    const float* tok_w = (const float*)d_in[1];
    const float* pe    = (const float*)d_in[2];
    const float* Wq    = (const float*)d_in[3];
    const float* bq    = (const float*)d_in[4];
    const float* Wk    = (const float*)d_in[5];
    const float* bk    = (const float*)d_in[6];
    const float* Wv    = (const float*)d_in[7];
    const float* bv    = (const float*)d_in[8];
    // d_in[9]/d_in[10] (Wsig/bsig): prior branch never reaches output -> skipped
    const float* Wo    = (const float*)d_in[11];
    const float* bo    = (const float*)d_in[12];
    const float* W1    = (const float*)d_in[13];
    const float* b1    = (const float*)d_in[14];
    const float* W2    = (const float*)d_in[15];
    const float* b2    = (const float*)d_in[16];
    const float* pw    = (const float*)d_in[17];
    const float* pb    = (const float*)d_in[18];
    float* out = (float*)d_out;

    float *h, *qkv, *bqkv;
    bf16 *h_hi, *h_lo, *o_hi, *o_lo, *y_hi, *y_lo, *xg_hi, *xg_lo;
    bf16 *wp_hi, *wp_lo, *wqkv_hi, *wqkv_lo, *wo_hi, *wo_lo;
    bf16 *w1_hi, *w1_lo, *w2_hi, *w2_lo, *pw_hi, *pw_lo;
    cudaGetSymbolAddress((void**)&h,    g_h);
    cudaGetSymbolAddress((void**)&qkv,  g_qkv);
    cudaGetSymbolAddress((void**)&bqkv, g_bqkv);
    cudaGetSymbolAddress((void**)&h_hi, g_h_hi);   cudaGetSymbolAddress((void**)&h_lo, g_h_lo);
    cudaGetSymbolAddress((void**)&o_hi, g_o_hi);   cudaGetSymbolAddress((void**)&o_lo, g_o_lo);
    cudaGetSymbolAddress((void**)&y_hi, g_y_hi);   cudaGetSymbolAddress((void**)&y_lo, g_y_lo);
    cudaGetSymbolAddress((void**)&xg_hi, g_xg_hi); cudaGetSymbolAddress((void**)&xg_lo, g_xg_lo);
    cudaGetSymbolAddress((void**)&wp_hi, g_wp_hi); cudaGetSymbolAddress((void**)&wp_lo, g_wp_lo);
    cudaGetSymbolAddress((void**)&wqkv_hi, g_wqkv_hi); cudaGetSymbolAddress((void**)&wqkv_lo, g_wqkv_lo);
    cudaGetSymbolAddress((void**)&wo_hi, g_wo_hi); cudaGetSymbolAddress((void**)&wo_lo, g_wo_lo);
    cudaGetSymbolAddress((void**)&w1_hi, g_w1_hi); cudaGetSymbolAddress((void**)&w1_lo, g_w1_lo);
    cudaGetSymbolAddress((void**)&w2_hi, g_w2_hi); cudaGetSymbolAddress((void**)&w2_lo, g_w2_lo);
    cudaGetSymbolAddress((void**)&pw_hi, g_pw_hi); cudaGetSymbolAddress((void**)&pw_lo, g_pw_lo);

    cudaFuncSetAttribute(attn_kernel,
                         cudaFuncAttributeMaxDynamicSharedMemorySize,
                         ATTN_SMEM_BYTES);

    // prep: im2col hilo, weight hilo conversions
    gather_kernel<<<(BL_ * KCP_ + 255) / 256, 256>>>(x);
    packw_kernel<<<(D_ * KCP_ + 255) / 256, 256>>>(tok_w);
    packqkv_kernel<<<(NL_ * QS_ * D_ + 255) / 256, 256>>>(Wq, Wk, Wv, bq, bk, bv);
    f2hl_kernel<<<(NL_ * D_ * D_ + 255) / 256, 256>>>(Wo, wo_hi, wo_lo, NL_ * D_ * D_);
    f2hl_kernel<<<(NL_ * DFF_ * D_ + 255) / 256, 256>>>(W1, w1_hi, w1_lo, NL_ * DFF_ * D_);
    f2hl_kernel<<<(NL_ * D_ * DFF_ + 255) / 256, 256>>>(W2, w2_hi, w2_lo, NL_ * D_ * DFF_);
    f2hl_kernel<<<(C_ * D_ + 255) / 256, 256>>>(pw, pw_hi, pw_lo, C_ * D_);

    // token embedding: h = xg @ wp^T + pe  (fp32 + hilo out)
    launch_one<3>(xg_hi, xg_lo, wp_hi, wp_lo, nullptr, h, h_hi, h_lo,
                  BL_, D_, KCP_, pe);

    for (int l = 0; l < NL_; ++l) {
        // fused QKV projection (fp32 out only)
        launch_one<0>(h_hi, h_lo,
                      wqkv_hi + (size_t)l * QS_ * D_, wqkv_lo + (size_t)l * QS_ * D_,
                      bqkv + (size_t)l * QS_, qkv, nullptr, nullptr,
                      BL_, QS_, D_, nullptr);

        attn_kernel<<<B_ * H_, 256, ATTN_SMEM_BYTES>>>(qkv, o_hi, o_lo);

        // h += o @ Wo^T + bo  (fp32 rmw + hilo out)
        launch_one<1>(o_hi, o_lo,
                      wo_hi + (size_t)l * D_ * D_, wo_lo + (size_t)l * D_ * D_,
                      bo + (size_t)l * D_, h, h_hi, h_lo,
                      BL_, D_, D_, nullptr);
        // y = gelu(h @ W1^T + b1)  (hilo out only)
        launch_one<2>(h_hi, h_lo,
                      w1_hi + (size_t)l * DFF_ * D_, w1_lo + (size_t)l * DFF_ * D_,
                      b1 + (size_t)l * DFF_, nullptr, y_hi, y_lo,
                      BL_, DFF_, D_, nullptr);
        // h += y @ W2^T + b2  (fp32 rmw + hilo out)
        launch_one<1>(y_hi, y_lo,
                      w2_hi + (size_t)l * D_ * DFF_, w2_lo + (size_t)l * D_ * DFF_,
                      b2 + (size_t)l * D_, h, h_hi, h_lo,
                      BL_, D_, DFF_, nullptr);
    }

    // final projection -> output [B, L, C]  (fp32 only)
    launch_one<0>(h_hi, h_lo, pw_hi, pw_lo, pb, out, nullptr, nullptr,
                  BL_, C_, D_, nullptr);
}